// round 3
// baseline (speedup 1.0000x reference)
#include <cuda_runtime.h>
#include <math.h>

#define BD 8
#define SL 2048
#define DM 256
#define HN 4
#define DH 64
#define MR (BD*SL)   // 16384

// Scratch (device globals; allocation-free per harness rules)
__device__ float g_qkv[MR*768];
__device__ float g_Q[BD*HN*SL*DH];
__device__ float g_K[BD*HN*SL*DH];
__device__ float g_V[BD*HN*SL*DH];
__device__ float g_ctx[MR*DM];
__device__ float g_msg[MR*DM];
__device__ float g_ff[MR*2*DM];

// ---------------------------------------------------------------------------
// Generic 64x64 tile GEMM: C = A @ W^T + bias, A[M,K] row-major, W[N,K] row-major
// MODE 0: plain C = acc + bias
// MODE 2: C = acc + bias + res  (residual add)
// CONCAT: logical A = concat(A, A2) along K; both have row stride 256
// ---------------------------------------------------------------------------
template<int MODE, bool CONCAT>
__global__ __launch_bounds__(256) void gemm64(
    const float* __restrict__ A, const float* __restrict__ A2,
    const float* __restrict__ W, const float* __restrict__ bias,
    float* __restrict__ C, const float* __restrict__ res,
    int M, int N, int K)
{
    __shared__ float As[16][64];   // [k][m]
    __shared__ float Ws[16][64];   // [k][n]
    const int t  = threadIdx.x;
    const int ty = t >> 4, tx = t & 15;
    const int m0 = blockIdx.y << 6, n0 = blockIdx.x << 6;
    const int lr = t >> 2, lk = (t & 3) << 2;

    float acc[4][4] = {};

    for (int k0 = 0; k0 < K; k0 += 16) {
        int kk = k0 + lk;
        const float* Ap = A;
        int astr = CONCAT ? 256 : K;
        if (CONCAT && kk >= 256) { Ap = A2; kk -= 256; }
        float4 av = *(const float4*)(Ap + (size_t)(m0 + lr) * astr + kk);
        float4 wv = *(const float4*)(W  + (size_t)(n0 + lr) * K + k0 + lk);
        __syncthreads();
        As[lk+0][lr] = av.x; As[lk+1][lr] = av.y; As[lk+2][lr] = av.z; As[lk+3][lr] = av.w;
        Ws[lk+0][lr] = wv.x; Ws[lk+1][lr] = wv.y; Ws[lk+2][lr] = wv.z; Ws[lk+3][lr] = wv.w;
        __syncthreads();
        #pragma unroll
        for (int k = 0; k < 16; k++) {
            float4 a = *(const float4*)&As[k][ty << 2];
            float4 b = *(const float4*)&Ws[k][tx << 2];
            acc[0][0] += a.x*b.x; acc[0][1] += a.x*b.y; acc[0][2] += a.x*b.z; acc[0][3] += a.x*b.w;
            acc[1][0] += a.y*b.x; acc[1][1] += a.y*b.y; acc[1][2] += a.y*b.z; acc[1][3] += a.y*b.w;
            acc[2][0] += a.z*b.x; acc[2][1] += a.z*b.y; acc[2][2] += a.z*b.z; acc[2][3] += a.z*b.w;
            acc[3][0] += a.w*b.x; acc[3][1] += a.w*b.y; acc[3][2] += a.w*b.z; acc[3][3] += a.w*b.w;
        }
    }

    #pragma unroll
    for (int i = 0; i < 4; i++) {
        int gm = m0 + (ty << 2) + i;
        #pragma unroll
        for (int j = 0; j < 4; j++) {
            int gn = n0 + (tx << 2) + j;
            float v = acc[i][j] + bias[gn];
            if (MODE == 0) {
                C[(size_t)gm * N + gn] = v;
            } else {
                C[(size_t)gm * N + gn] = v + res[(size_t)gm * N + gn];
            }
        }
    }
}

// ---------------------------------------------------------------------------
// Repack qkv [M,768] -> g_Q/g_K/g_V [B,H,S,Dh] with RoPE applied to Q,K.
// qkv col layout (reference reshape (H, Dh, 3)): col = h*192 + d*3 + c.
// For a pair d = 2*d2, 2*d2+1 the 6 values (q0,k0,v0,q1,k1,v1) are contiguous
// at base = h*192 + 6*d2.
// keypoints kp: [2, B, 1, S, Dh]; cos at offset 0, sin at B*S*Dh.
// rotate_half: out[2i] = -x[2i+1], out[2i+1] = x[2i]
//   q'[2i]   = q0*cos[2i]   - q1*sin[2i]
//   q'[2i+1] = q1*cos[2i+1] + q0*sin[2i+1]
// ---------------------------------------------------------------------------
__global__ __launch_bounds__(256) void repack_rope_kernel(const float* __restrict__ kp)
{
    int idx = blockIdx.x * blockDim.x + threadIdx.x;   // over B*H*S*32 pairs
    int d2 = idx & 31;                 // pair index within head dim
    int s  = (idx >> 5) & (SL - 1);
    int h  = (idx >> 16) & (HN - 1);
    int b  = idx >> 18;

    int gm = b * SL + s;
    const float* src = g_qkv + (size_t)gm * 768 + h * 192 + 6 * d2;
    float q0 = src[0], k0 = src[1], v0 = src[2];
    float q1 = src[3], k1 = src[4], v1 = src[5];

    const int SIN_OFF = BD * SL * DH;
    int kb = (b * SL + s) * DH + (d2 << 1);
    float c0 = kp[kb],           c1 = kp[kb + 1];
    float s0 = kp[SIN_OFF + kb], s1 = kp[SIN_OFF + kb + 1];

    int base = (((b * HN + h) * SL) + s) * DH + (d2 << 1);
    g_Q[base]     = q0 * c0 - q1 * s0;
    g_Q[base + 1] = q1 * c1 + q0 * s1;
    g_K[base]     = k0 * c0 - k1 * s0;
    g_K[base + 1] = k1 * c1 + k0 * s1;
    g_V[base]     = v0;
    g_V[base + 1] = v1;
}

// ---------------------------------------------------------------------------
// Flash-style attention, fp32, max-free softmax (softmax is shift-invariant
// and with correct data logits are O(1), far below exp() overflow).
// Block = 64 queries x full key stream in 64-key tiles.
// ---------------------------------------------------------------------------
__global__ __launch_bounds__(256) void attn_kernel(float* __restrict__ ctx)
{
    __shared__ float Qs[64][64];    // [d][m]  (Q^T, scale folded)
    __shared__ float KPs[64][64];   // K as [d][n], then P=exp(S) as [m][j]
    __shared__ float Vs[64][64];    // [n][d]

    const int t  = threadIdx.x;
    const int ty = t >> 4, tx = t & 15;
    const int bh = blockIdx.y;
    const int m0 = blockIdx.x << 6;
    const int lr = t >> 2;             // row 0..63
    const int lk = (t & 3) << 2;       // col base 0,4,8,12

    const float* Qb = g_Q + (size_t)bh * SL * DH;
    const float* Kb = g_K + (size_t)bh * SL * DH;
    const float* Vb = g_V + (size_t)bh * SL * DH;
    const float scale = 0.125f;  // Dh^-0.5

    // Load full 64x64 Q tile (transposed, scale folded): 4 float4 per thread
    #pragma unroll
    for (int c = 0; c < 4; c++) {
        int col = lk + (c << 4);   // 0..60
        float4 qv = *(const float4*)(Qb + (size_t)(m0 + lr) * DH + col);
        Qs[col+0][lr] = qv.x * scale; Qs[col+1][lr] = qv.y * scale;
        Qs[col+2][lr] = qv.z * scale; Qs[col+3][lr] = qv.w * scale;
    }

    float o[4][4] = {};
    float l[4]  = {};

    for (int n0 = 0; n0 < SL; n0 += 64) {
        __syncthreads();   // protect Qs store (1st iter) / prev-iter PV reads
        #pragma unroll
        for (int c = 0; c < 4; c++) {
            int col = lk + (c << 4);
            float4 kv = *(const float4*)(Kb + (size_t)(n0 + lr) * DH + col);
            KPs[col+0][lr] = kv.x; KPs[col+1][lr] = kv.y;
            KPs[col+2][lr] = kv.z; KPs[col+3][lr] = kv.w;
            float4 vv = *(const float4*)(Vb + (size_t)(n0 + lr) * DH + col);
            *(float4*)&Vs[lr][col] = vv;
        }
        __syncthreads();

        // S tile = (scaled Q) K^T
        float s[4][4] = {};
        #pragma unroll
        for (int d = 0; d < 64; d++) {
            float4 a = *(const float4*)&Qs[d][ty << 2];
            float4 b = *(const float4*)&KPs[d][tx << 2];
            s[0][0] += a.x*b.x; s[0][1] += a.x*b.y; s[0][2] += a.x*b.z; s[0][3] += a.x*b.w;
            s[1][0] += a.y*b.x; s[1][1] += a.y*b.y; s[1][2] += a.y*b.z; s[1][3] += a.y*b.w;
            s[2][0] += a.z*b.x; s[2][1] += a.z*b.y; s[2][2] += a.z*b.z; s[2][3] += a.z*b.w;
            s[3][0] += a.w*b.x; s[3][1] += a.w*b.y; s[3][2] += a.w*b.z; s[3][3] += a.w*b.w;
        }

        // P = exp(S); accumulate row sums (16 lanes per row group)
        #pragma unroll
        for (int i = 0; i < 4; i++) {
            float rs = 0.f;
            #pragma unroll
            for (int j = 0; j < 4; j++) { s[i][j] = __expf(s[i][j]); rs += s[i][j]; }
            #pragma unroll
            for (int off = 1; off < 16; off <<= 1)
                rs += __shfl_xor_sync(0xffffffffu, rs, off);
            l[i] += rs;
        }

        __syncthreads();   // done reading KPs as K
        #pragma unroll
        for (int i = 0; i < 4; i++)
            #pragma unroll
            for (int j = 0; j < 4; j++)
                KPs[(ty << 2) + i][(tx << 2) + j] = s[i][j];   // P, [m][j]
        __syncthreads();

        // O += P V
        #pragma unroll
        for (int j = 0; j < 64; j++) {
            float a0 = KPs[(ty << 2) + 0][j];
            float a1 = KPs[(ty << 2) + 1][j];
            float a2 = KPs[(ty << 2) + 2][j];
            float a3 = KPs[(ty << 2) + 3][j];
            float4 b = *(const float4*)&Vs[j][tx << 2];
            o[0][0] += a0*b.x; o[0][1] += a0*b.y; o[0][2] += a0*b.z; o[0][3] += a0*b.w;
            o[1][0] += a1*b.x; o[1][1] += a1*b.y; o[1][2] += a1*b.z; o[1][3] += a1*b.w;
            o[2][0] += a2*b.x; o[2][1] += a2*b.y; o[2][2] += a2*b.z; o[2][3] += a2*b.w;
            o[3][0] += a3*b.x; o[3][1] += a3*b.y; o[3][2] += a3*b.z; o[3][3] += a3*b.w;
        }
    }

    const int b = bh >> 2, h = bh & 3;
    #pragma unroll
    for (int i = 0; i < 4; i++) {
        float inv = 1.0f / l[i];
        size_t row = (size_t)(b * SL + m0 + (ty << 2) + i) * DM + h * DH + (tx << 2);
        float4 v = make_float4(o[i][0]*inv, o[i][1]*inv, o[i][2]*inv, o[i][3]*inv);
        *(float4*)(ctx + row) = v;
    }
}

// ---------------------------------------------------------------------------
// LayerNorm (biased var) + exact GELU, in place on g_ff rows of 512
// ---------------------------------------------------------------------------
__global__ __launch_bounds__(256) void ln_gelu_kernel(const float* __restrict__ g,
                                                      const float* __restrict__ bb)
{
    int row = blockIdx.x;
    float* xr = g_ff + (size_t)row * 512;
    int t = threadIdx.x;
    float v0 = xr[t], v1 = xr[t + 256];
    float sum = v0 + v1;
    float sq  = v0 * v0 + v1 * v1;
    #pragma unroll
    for (int off = 16; off > 0; off >>= 1) {
        sum += __shfl_xor_sync(0xffffffffu, sum, off);
        sq  += __shfl_xor_sync(0xffffffffu, sq,  off);
    }
    __shared__ float ssum[8], ssq[8];
    __shared__ float smean, srstd;
    int w = t >> 5;
    if ((t & 31) == 0) { ssum[w] = sum; ssq[w] = sq; }
    __syncthreads();
    if (t == 0) {
        float S = 0.f, Q = 0.f;
        #pragma unroll
        for (int i = 0; i < 8; i++) { S += ssum[i]; Q += ssq[i]; }
        float mean = S * (1.0f / 512.0f);
        float var  = Q * (1.0f / 512.0f) - mean * mean;
        smean = mean;
        srstd = rsqrtf(var + 1e-5f);
    }
    __syncthreads();
    float mean = smean, rstd = srstd;

    float y0 = (v0 - mean) * rstd * g[t] + bb[t];
    float y1 = (v1 - mean) * rstd * g[t + 256] + bb[t + 256];
    xr[t]       = 0.5f * y0 * (1.0f + erff(y0 * 0.70710678118654752f));
    xr[t + 256] = 0.5f * y1 * (1.0f + erff(y1 * 0.70710678118654752f));
}

// ---------------------------------------------------------------------------
extern "C" void kernel_launch(void* const* d_in, const int* in_sizes, int n_in,
                              void* d_out, int out_size)
{
    (void)in_sizes; (void)n_in; (void)out_size;
    const float* desc   = (const float*)d_in[0];
    const float* kp     = (const float*)d_in[1];
    const float* Wqkv_w = (const float*)d_in[2];
    const float* Wqkv_b = (const float*)d_in[3];
    const float* Wo_w   = (const float*)d_in[4];
    const float* Wo_b   = (const float*)d_in[5];
    const float* W1_w   = (const float*)d_in[6];
    const float* W1_b   = (const float*)d_in[7];
    const float* ln_g   = (const float*)d_in[8];
    const float* ln_b   = (const float*)d_in[9];
    const float* W2_w   = (const float*)d_in[10];
    const float* W2_b   = (const float*)d_in[11];
    float* out = (float*)d_out;

    float *pqkv = nullptr, *pctx = nullptr, *pmsg = nullptr, *pff = nullptr;
    cudaGetSymbolAddress((void**)&pqkv, g_qkv);
    cudaGetSymbolAddress((void**)&pctx, g_ctx);
    cudaGetSymbolAddress((void**)&pmsg, g_msg);
    cudaGetSymbolAddress((void**)&pff,  g_ff);

    // 1. QKV projection (plain GEMM, [M,768])
    gemm64<0, false><<<dim3(768 / 64, MR / 64), 256>>>(
        desc, nullptr, Wqkv_w, Wqkv_b, pqkv, nullptr, MR, 768, 256);

    // 2. Repack to [B,H,S,Dh] + RoPE on Q,K
    repack_rope_kernel<<<(BD * HN * SL * 32) / 256, 256>>>(kp);

    // 3. Attention -> ctx [B,S,D]
    attn_kernel<<<dim3(SL / 64, BD * HN), 256>>>(pctx);

    // 4. message = ctx @ Wo^T + b
    gemm64<0, false><<<dim3(DM / 64, MR / 64), 256>>>(
        pctx, nullptr, Wo_w, Wo_b, pmsg, nullptr, MR, DM, DM);

    // 5. ff = concat(desc, msg) @ W1^T + b   (concat read on the fly)
    gemm64<0, true><<<dim3(512 / 64, MR / 64), 256>>>(
        desc, pmsg, W1_w, W1_b, pff, nullptr, MR, 512, 512);

    // 6. LayerNorm + GELU in place
    ln_gelu_kernel<<<MR, 256>>>(ln_g, ln_b);

    // 7. out = desc + ff @ W2^T + b
    gemm64<2, false><<<dim3(DM / 64, MR / 64), 256>>>(
        pff, nullptr, W2_w, W2_b, out, desc, MR, DM, 512);
}

// round 4
// speedup vs baseline: 2.6641x; 2.6641x over previous
#include <cuda_runtime.h>
#include <math.h>
#include <stdint.h>

#define BD 8
#define SL 2048
#define DM 256
#define HN 4
#define DH 64
#define MR (BD*SL)   // 16384

// Scratch (device globals; allocation-free per harness rules)
__device__ float g_qkv[MR*768];
__device__ float g_Q[BD*HN*SL*DH];
__device__ float g_K[BD*HN*SL*DH];
__device__ float g_V[BD*HN*SL*DH];
__device__ float g_ctx[MR*DM];
__device__ float g_msg[MR*DM];
__device__ float g_ff[MR*2*DM];

// ---- TF32 helpers -----------------------------------------------------------
__device__ __forceinline__ uint32_t f2tf_hi(float x) {
    return __float_as_uint(x) & 0xffffe000u;          // truncate to tf32 (valid pattern)
}
__device__ __forceinline__ uint32_t f2tf_lo(float x, uint32_t hi) {
    float lo = x - __uint_as_float(hi);
    return __float_as_uint(lo) & 0xffffe000u;
}
__device__ __forceinline__ void mma8(float* c, const uint32_t* a, uint32_t b0, uint32_t b1) {
    asm volatile(
        "mma.sync.aligned.m16n8k8.row.col.f32.tf32.tf32.f32 "
        "{%0,%1,%2,%3},{%4,%5,%6,%7},{%8,%9},{%0,%1,%2,%3};"
        : "+f"(c[0]), "+f"(c[1]), "+f"(c[2]), "+f"(c[3])
        : "r"(a[0]), "r"(a[1]), "r"(a[2]), "r"(a[3]), "r"(b0), "r"(b1));
}

// ---------------------------------------------------------------------------
// Tensor-core GEMM (3xTF32): C = A @ W^T + bias, A[M,K] rm, W[N,K] rm.
// BM=128, BN=64, BK=16. 256 threads = 8 warps (4 M x 2 N), warp tile 32x32.
// MODE 0: C = acc + bias;  MODE 2: C = acc + bias + res
// CONCAT: logical A = concat(A, A2) along K, both row stride 256
// ---------------------------------------------------------------------------
#define AST 20   // smem k-stride (16+4): banks (4m+k)%32 distinct within quad groups
template<int MODE, bool CONCAT>
__global__ __launch_bounds__(256) void gemm_tc(
    const float* __restrict__ A, const float* __restrict__ A2,
    const float* __restrict__ W, const float* __restrict__ bias,
    float* __restrict__ C, const float* __restrict__ res,
    int M, int N, int K)
{
    __shared__ uint32_t Ah[128*AST], Al[128*AST], Bh[64*AST], Bl[64*AST];
    const int t = threadIdx.x;
    const int w = t >> 5, wm = w & 3, wn = w >> 2;
    const int lane = t & 31, lr4 = lane >> 2, lc4 = lane & 3;
    const int m0 = blockIdx.y << 7, n0 = blockIdx.x << 6;

    float acc[2][4][4] = {};

    const int ar = t >> 1, acb = (t & 1) << 3;   // A: 2 thr/row, 8 floats each
    const int br = t >> 2, bcb = (t & 3) << 2;   // B: 4 thr/row, 4 floats each

    for (int k0 = 0; k0 < K; k0 += 16) {
        // global loads into registers (overlap previous mma)
        int kk = k0 + acb;
        const float* asrc;
        if (CONCAT) asrc = (kk >= 256) ? (A2 + (size_t)(m0 + ar) * 256 + kk - 256)
                                       : (A  + (size_t)(m0 + ar) * 256 + kk);
        else        asrc = A + (size_t)(m0 + ar) * K + kk;
        float4 a1 = *(const float4*)asrc;
        float4 a2 = *(const float4*)(asrc + 4);
        float4 bv = *(const float4*)(W + (size_t)(n0 + br) * K + k0 + bcb);

        __syncthreads();   // previous mma done reading smem
        {
            float av[8] = {a1.x,a1.y,a1.z,a1.w,a2.x,a2.y,a2.z,a2.w};
            #pragma unroll
            for (int i = 0; i < 8; i++) {
                uint32_t h = f2tf_hi(av[i]);
                Ah[ar*AST + acb + i] = h;
                Al[ar*AST + acb + i] = f2tf_lo(av[i], h);
            }
            float bvv[4] = {bv.x,bv.y,bv.z,bv.w};
            #pragma unroll
            for (int i = 0; i < 4; i++) {
                uint32_t h = f2tf_hi(bvv[i]);
                Bh[br*AST + bcb + i] = h;
                Bl[br*AST + bcb + i] = f2tf_lo(bvv[i], h);
            }
        }
        __syncthreads();

        #pragma unroll
        for (int ks = 0; ks < 2; ks++) {
            const int kb = ks << 3;
            uint32_t ah[2][4], al[2][4];
            #pragma unroll
            for (int mi = 0; mi < 2; mi++) {
                int r = wm*32 + mi*16 + lr4, c = kb + lc4;
                ah[mi][0] = Ah[r*AST + c];     ah[mi][1] = Ah[(r+8)*AST + c];
                ah[mi][2] = Ah[r*AST + c + 4]; ah[mi][3] = Ah[(r+8)*AST + c + 4];
                al[mi][0] = Al[r*AST + c];     al[mi][1] = Al[(r+8)*AST + c];
                al[mi][2] = Al[r*AST + c + 4]; al[mi][3] = Al[(r+8)*AST + c + 4];
            }
            #pragma unroll
            for (int ni = 0; ni < 4; ni++) {
                int r = wn*32 + ni*8 + lr4, c = kb + lc4;
                uint32_t bh0 = Bh[r*AST + c], bh1 = Bh[r*AST + c + 4];
                uint32_t bl0 = Bl[r*AST + c], bl1 = Bl[r*AST + c + 4];
                #pragma unroll
                for (int mi = 0; mi < 2; mi++) {
                    mma8(acc[mi][ni], ah[mi], bh0, bh1);
                    mma8(acc[mi][ni], ah[mi], bl0, bl1);
                    mma8(acc[mi][ni], al[mi], bh0, bh1);
                }
            }
        }
    }

    // epilogue
    #pragma unroll
    for (int mi = 0; mi < 2; mi++) {
        #pragma unroll
        for (int ni = 0; ni < 4; ni++) {
            int gm = m0 + wm*32 + mi*16 + lr4;
            int gn = n0 + wn*32 + ni*8 + 2*lc4;
            float b0 = bias[gn], b1 = bias[gn+1];
            float v00 = acc[mi][ni][0] + b0, v01 = acc[mi][ni][1] + b1;
            float v10 = acc[mi][ni][2] + b0, v11 = acc[mi][ni][3] + b1;
            if (MODE == 2) {
                const float* r0 = res + (size_t)gm * N + gn;
                const float* r1 = res + (size_t)(gm+8) * N + gn;
                v00 += r0[0]; v01 += r0[1]; v10 += r1[0]; v11 += r1[1];
            }
            *(float2*)(C + (size_t)gm * N + gn)     = make_float2(v00, v01);
            *(float2*)(C + (size_t)(gm+8) * N + gn) = make_float2(v10, v11);
        }
    }
}

// ---------------------------------------------------------------------------
// Repack qkv [M,768] -> g_Q/g_K/g_V [B,H,S,Dh] with RoPE applied to Q,K.
// qkv col = h*192 + d*3 + c ; pair (q0,k0,v0,q1,k1,v1) contiguous at h*192+6*d2
// ---------------------------------------------------------------------------
__global__ __launch_bounds__(256) void repack_rope_kernel(const float* __restrict__ kp)
{
    int idx = blockIdx.x * blockDim.x + threadIdx.x;   // B*H*S*32 pairs
    int d2 = idx & 31;
    int s  = (idx >> 5) & (SL - 1);
    int h  = (idx >> 16) & (HN - 1);
    int b  = idx >> 18;

    int gm = b * SL + s;
    const float* src = g_qkv + (size_t)gm * 768 + h * 192 + 6 * d2;
    float q0 = src[0], k0 = src[1], v0 = src[2];
    float q1 = src[3], k1 = src[4], v1 = src[5];

    const int SIN_OFF = BD * SL * DH;
    int kb = (b * SL + s) * DH + (d2 << 1);
    float c0 = kp[kb],           c1 = kp[kb + 1];
    float s0 = kp[SIN_OFF + kb], s1 = kp[SIN_OFF + kb + 1];

    int base = (((b * HN + h) * SL) + s) * DH + (d2 << 1);
    g_Q[base]     = q0 * c0 - q1 * s0;
    g_Q[base + 1] = q1 * c1 + q0 * s1;
    g_K[base]     = k0 * c0 - k1 * s0;
    g_K[base + 1] = k1 * c1 + k0 * s1;
    g_V[base]     = v0;
    g_V[base + 1] = v1;
}

// ---------------------------------------------------------------------------
// Flash attention, TF32 mma, max-free softmax.
// CTA: 64 queries x full key stream (64-key tiles). 8 warps: 4(M) x 2(N).
// Q fragments live in registers for the whole CTA. P overlays the K tile.
// ---------------------------------------------------------------------------
#define KST 68   // K/P smem stride
#define VST 72   // V smem stride (conflict-free B-frag: (8k+n)%32 distinct)
__global__ __launch_bounds__(256) void attn_kernel(float* __restrict__ ctx)
{
    __shared__ uint32_t KPs[64*KST];
    __shared__ uint32_t Vs[64*VST];
    __shared__ float lsum[2][64];

    const int t = threadIdx.x;
    const int w = t >> 5, wm = w & 3, wn = w >> 2;
    const int lane = t & 31, lr4 = lane >> 2, lc4 = lane & 3;
    const int bh = blockIdx.y;
    const int m0 = blockIdx.x << 6;

    const float* Qb = g_Q + (size_t)bh * SL * DH;
    const float* Kb = g_K + (size_t)bh * SL * DH;
    const float* Vb = g_V + (size_t)bh * SL * DH;
    const float scale = 0.125f;

    // Q fragments in registers (tf32, scale folded): 8 k-steps x 4 regs
    uint32_t qf[8][4];
    {
        int r = m0 + wm*16 + lr4;
        #pragma unroll
        for (int kk = 0; kk < 8; kk++) {
            int c = kk*8 + lc4;
            qf[kk][0] = f2tf_hi(Qb[(size_t)r     * DH + c]     * scale);
            qf[kk][1] = f2tf_hi(Qb[(size_t)(r+8) * DH + c]     * scale);
            qf[kk][2] = f2tf_hi(Qb[(size_t)r     * DH + c + 4] * scale);
            qf[kk][3] = f2tf_hi(Qb[(size_t)(r+8) * DH + c + 4] * scale);
        }
    }

    float o[4][4] = {};
    float l0 = 0.f, l1 = 0.f;

    const int ldr = t >> 2, ldc = (t & 3) << 2;   // loader: row, col base

    for (int n0 = 0; n0 < SL; n0 += 64) {
        __syncthreads();   // prev PV reads done
        #pragma unroll
        for (int c = 0; c < 4; c++) {
            int col = ldc + (c << 4);
            float4 kv = *(const float4*)(Kb + (size_t)(n0 + ldr) * DH + col);
            KPs[ldr*KST + col + 0] = f2tf_hi(kv.x);
            KPs[ldr*KST + col + 1] = f2tf_hi(kv.y);
            KPs[ldr*KST + col + 2] = f2tf_hi(kv.z);
            KPs[ldr*KST + col + 3] = f2tf_hi(kv.w);
            float4 vv = *(const float4*)(Vb + (size_t)(n0 + ldr) * DH + col);
            Vs[ldr*VST + col + 0] = f2tf_hi(vv.x);
            Vs[ldr*VST + col + 1] = f2tf_hi(vv.y);
            Vs[ldr*VST + col + 2] = f2tf_hi(vv.z);
            Vs[ldr*VST + col + 3] = f2tf_hi(vv.w);
        }
        __syncthreads();

        // S = Q K^T  (warp tile 16 x 32)
        float s[4][4] = {};
        #pragma unroll
        for (int kk = 0; kk < 8; kk++) {
            #pragma unroll
            for (int ni = 0; ni < 4; ni++) {
                int n = wn*32 + ni*8 + lr4;
                uint32_t b0 = KPs[n*KST + kk*8 + lc4];
                uint32_t b1 = KPs[n*KST + kk*8 + lc4 + 4];
                mma8(s[ni], qf[kk], b0, b1);
            }
        }

        // P = exp(S), partial row sums
        float rs0 = 0.f, rs1 = 0.f;
        #pragma unroll
        for (int ni = 0; ni < 4; ni++) {
            s[ni][0] = __expf(s[ni][0]); s[ni][1] = __expf(s[ni][1]);
            s[ni][2] = __expf(s[ni][2]); s[ni][3] = __expf(s[ni][3]);
            rs0 += s[ni][0] + s[ni][1];
            rs1 += s[ni][2] + s[ni][3];
        }
        rs0 += __shfl_xor_sync(0xffffffffu, rs0, 1);
        rs0 += __shfl_xor_sync(0xffffffffu, rs0, 2);
        rs1 += __shfl_xor_sync(0xffffffffu, rs1, 1);
        rs1 += __shfl_xor_sync(0xffffffffu, rs1, 2);
        l0 += rs0; l1 += rs1;

        __syncthreads();   // all warps done reading K tile
        {
            int pr = wm*16 + lr4;
            #pragma unroll
            for (int ni = 0; ni < 4; ni++) {
                int pc = wn*32 + ni*8 + 2*lc4;
                KPs[pr*KST + pc]     = f2tf_hi(s[ni][0]);
                KPs[pr*KST + pc + 1] = f2tf_hi(s[ni][1]);
                KPs[(pr+8)*KST + pc]     = f2tf_hi(s[ni][2]);
                KPs[(pr+8)*KST + pc + 1] = f2tf_hi(s[ni][3]);
            }
        }
        __syncthreads();

        // O += P V   (warp tile 16 x 32 over d)
        #pragma unroll
        for (int kk = 0; kk < 8; kk++) {
            int ar = wm*16 + lr4, ac = kk*8 + lc4;
            uint32_t a[4] = { KPs[ar*KST + ac], KPs[(ar+8)*KST + ac],
                              KPs[ar*KST + ac + 4], KPs[(ar+8)*KST + ac + 4] };
            #pragma unroll
            for (int ni = 0; ni < 4; ni++) {
                int vc = wn*32 + ni*8 + lr4;
                uint32_t b0 = Vs[(kk*8 + lc4)*VST + vc];
                uint32_t b1 = Vs[(kk*8 + lc4 + 4)*VST + vc];
                mma8(o[ni], a, b0, b1);
            }
        }
    }

    // combine row sums across the 2 N-warps
    {
        int pr = wm*16 + lr4;
        if (lc4 == 0) { lsum[wn][pr] = l0; lsum[wn][pr + 8] = l1; }
    }
    __syncthreads();
    {
        int pr = wm*16 + lr4;
        float inv0 = 1.0f / (lsum[0][pr]     + lsum[1][pr]);
        float inv1 = 1.0f / (lsum[0][pr + 8] + lsum[1][pr + 8]);
        const int b = bh >> 2, h = bh & 3;
        size_t r0 = (size_t)(b * SL + m0 + pr) * DM + h * DH;
        size_t r1 = r0 + 8 * DM;
        #pragma unroll
        for (int ni = 0; ni < 4; ni++) {
            int d = wn*32 + ni*8 + 2*lc4;
            *(float2*)(ctx + r0 + d) = make_float2(o[ni][0]*inv0, o[ni][1]*inv0);
            *(float2*)(ctx + r1 + d) = make_float2(o[ni][2]*inv1, o[ni][3]*inv1);
        }
    }
}

// ---------------------------------------------------------------------------
// LayerNorm (biased var) + exact GELU, in place on g_ff rows of 512
// ---------------------------------------------------------------------------
__global__ __launch_bounds__(256) void ln_gelu_kernel(const float* __restrict__ g,
                                                      const float* __restrict__ bb)
{
    int row = blockIdx.x;
    float* xr = g_ff + (size_t)row * 512;
    int t = threadIdx.x;
    float v0 = xr[t], v1 = xr[t + 256];
    float sum = v0 + v1;
    float sq  = v0 * v0 + v1 * v1;
    #pragma unroll
    for (int off = 16; off > 0; off >>= 1) {
        sum += __shfl_xor_sync(0xffffffffu, sum, off);
        sq  += __shfl_xor_sync(0xffffffffu, sq,  off);
    }
    __shared__ float ssum[8], ssq[8];
    __shared__ float smean, srstd;
    int w = t >> 5;
    if ((t & 31) == 0) { ssum[w] = sum; ssq[w] = sq; }
    __syncthreads();
    if (t == 0) {
        float S = 0.f, Q = 0.f;
        #pragma unroll
        for (int i = 0; i < 8; i++) { S += ssum[i]; Q += ssq[i]; }
        float mean = S * (1.0f / 512.0f);
        float var  = Q * (1.0f / 512.0f) - mean * mean;
        smean = mean;
        srstd = rsqrtf(var + 1e-5f);
    }
    __syncthreads();
    float mean = smean, rstd = srstd;

    float y0 = (v0 - mean) * rstd * g[t] + bb[t];
    float y1 = (v1 - mean) * rstd * g[t + 256] + bb[t + 256];
    xr[t]       = 0.5f * y0 * (1.0f + erff(y0 * 0.70710678118654752f));
    xr[t + 256] = 0.5f * y1 * (1.0f + erff(y1 * 0.70710678118654752f));
}

// ---------------------------------------------------------------------------
extern "C" void kernel_launch(void* const* d_in, const int* in_sizes, int n_in,
                              void* d_out, int out_size)
{
    (void)in_sizes; (void)n_in; (void)out_size;
    const float* desc   = (const float*)d_in[0];
    const float* kp     = (const float*)d_in[1];
    const float* Wqkv_w = (const float*)d_in[2];
    const float* Wqkv_b = (const float*)d_in[3];
    const float* Wo_w   = (const float*)d_in[4];
    const float* Wo_b   = (const float*)d_in[5];
    const float* W1_w   = (const float*)d_in[6];
    const float* W1_b   = (const float*)d_in[7];
    const float* ln_g   = (const float*)d_in[8];
    const float* ln_b   = (const float*)d_in[9];
    const float* W2_w   = (const float*)d_in[10];
    const float* W2_b   = (const float*)d_in[11];
    float* out = (float*)d_out;

    float *pqkv = nullptr, *pctx = nullptr, *pmsg = nullptr, *pff = nullptr;
    cudaGetSymbolAddress((void**)&pqkv, g_qkv);
    cudaGetSymbolAddress((void**)&pctx, g_ctx);
    cudaGetSymbolAddress((void**)&pmsg, g_msg);
    cudaGetSymbolAddress((void**)&pff,  g_ff);

    // 1. QKV projection
    gemm_tc<0, false><<<dim3(768 / 64, MR / 128), 256>>>(
        desc, nullptr, Wqkv_w, Wqkv_b, pqkv, nullptr, MR, 768, 256);

    // 2. Repack to [B,H,S,Dh] + RoPE
    repack_rope_kernel<<<(BD * HN * SL * 32) / 256, 256>>>(kp);

    // 3. Attention -> ctx [B,S,D]
    attn_kernel<<<dim3(SL / 64, BD * HN), 256>>>(pctx);

    // 4. message = ctx @ Wo^T + b
    gemm_tc<0, false><<<dim3(DM / 64, MR / 128), 256>>>(
        pctx, nullptr, Wo_w, Wo_b, pmsg, nullptr, MR, DM, DM);

    // 5. ff = concat(desc, msg) @ W1^T + b
    gemm_tc<0, true><<<dim3(512 / 64, MR / 128), 256>>>(
        desc, pmsg, W1_w, W1_b, pff, nullptr, MR, 512, 512);

    // 6. LayerNorm + GELU in place
    ln_gelu_kernel<<<MR, 256>>>(ln_g, ln_b);

    // 7. out = desc + ff @ W2^T + b
    gemm_tc<2, false><<<dim3(DM / 64, MR / 128), 256>>>(
        pff, nullptr, W2_w, W2_b, out, desc, MR, DM, 512);
}

// round 5
// speedup vs baseline: 3.7202x; 1.3964x over previous
#include <cuda_runtime.h>
#include <math.h>
#include <stdint.h>

#define BD 8
#define SL 2048
#define DM 256
#define HN 4
#define DH 64
#define MR (BD*SL)   // 16384

// Scratch (device globals; allocation-free per harness rules)
__device__ float g_qkv[MR*768];
__device__ float g_Q[BD*HN*SL*DH];
__device__ float g_K[BD*HN*SL*DH];
__device__ float g_V[BD*HN*SL*DH];
__device__ float g_ctx[MR*DM];
__device__ float g_msg[MR*DM];
__device__ float g_ff[MR*2*DM];

// ---- TF32 helpers -----------------------------------------------------------
__device__ __forceinline__ uint32_t f2tf_hi(float x) {
    return __float_as_uint(x) & 0xffffe000u;          // truncate to tf32
}
__device__ __forceinline__ void mma8(float* c, const uint32_t* a, uint32_t b0, uint32_t b1) {
    asm volatile(
        "mma.sync.aligned.m16n8k8.row.col.f32.tf32.tf32.f32 "
        "{%0,%1,%2,%3},{%4,%5,%6,%7},{%8,%9},{%0,%1,%2,%3};"
        : "+f"(c[0]), "+f"(c[1]), "+f"(c[2]), "+f"(c[3])
        : "r"(a[0]), "r"(a[1]), "r"(a[2]), "r"(a[3]), "r"(b0), "r"(b1));
}

// ---------------------------------------------------------------------------
// Tensor-core GEMM (single TF32, double-buffered): C = A @ W^T + bias.
// A[M,K] rm, W[N,K] rm. BM=128, BN=64, BK=16.
// 256 threads = 8 warps (4 M x 2 N), warp tile 32x32.
// MODE 0: C = acc + bias;  MODE 2: C = acc + bias + res
// CONCAT: logical A = concat(A, A2) along K, both row stride 256
// ---------------------------------------------------------------------------
#define AST 20   // smem k-stride (16+4)
template<int MODE, bool CONCAT>
__global__ __launch_bounds__(256) void gemm_tc(
    const float* __restrict__ A, const float* __restrict__ A2,
    const float* __restrict__ W, const float* __restrict__ bias,
    float* __restrict__ C, const float* __restrict__ res,
    int M, int N, int K)
{
    __shared__ uint32_t Ah[2][128*AST], Bh[2][64*AST];
    const int t = threadIdx.x;
    const int w = t >> 5, wm = w & 3, wn = w >> 2;
    const int lane = t & 31, lr4 = lane >> 2, lc4 = lane & 3;
    const int m0 = blockIdx.y << 7, n0 = blockIdx.x << 6;

    float acc[2][4][4] = {};

    const int ar = t >> 1, acb = (t & 1) << 3;   // A: 2 thr/row, 8 floats each
    const int br = t >> 2, bcb = (t & 3) << 2;   // B: 4 thr/row, 4 floats each

    auto load_tile = [&](int k0, float4& a1, float4& a2, float4& bv) {
        int kk = k0 + acb;
        const float* asrc;
        if (CONCAT) asrc = (kk >= 256) ? (A2 + (size_t)(m0 + ar) * 256 + kk - 256)
                                       : (A  + (size_t)(m0 + ar) * 256 + kk);
        else        asrc = A + (size_t)(m0 + ar) * K + kk;
        a1 = *(const float4*)asrc;
        a2 = *(const float4*)(asrc + 4);
        bv = *(const float4*)(W + (size_t)(n0 + br) * K + k0 + bcb);
    };
    auto store_tile = [&](int buf, const float4& a1, const float4& a2, const float4& bv) {
        float av[8] = {a1.x,a1.y,a1.z,a1.w,a2.x,a2.y,a2.z,a2.w};
        #pragma unroll
        for (int i = 0; i < 8; i++) Ah[buf][ar*AST + acb + i] = f2tf_hi(av[i]);
        float bw[4] = {bv.x,bv.y,bv.z,bv.w};
        #pragma unroll
        for (int i = 0; i < 4; i++) Bh[buf][br*AST + bcb + i] = f2tf_hi(bw[i]);
    };

    // prologue: tile 0 into buffer 0
    {
        float4 a1, a2, bv;
        load_tile(0, a1, a2, bv);
        store_tile(0, a1, a2, bv);
    }
    __syncthreads();

    for (int k0 = 0; k0 < K; k0 += 16) {
        const int cur = (k0 >> 4) & 1;
        const bool more = (k0 + 16) < K;
        float4 na1, na2, nbv;
        if (more) load_tile(k0 + 16, na1, na2, nbv);   // LDG overlaps mma below

        #pragma unroll
        for (int ks = 0; ks < 2; ks++) {
            const int kb = ks << 3;
            uint32_t a[2][4];
            #pragma unroll
            for (int mi = 0; mi < 2; mi++) {
                int r = wm*32 + mi*16 + lr4, c = kb + lc4;
                a[mi][0] = Ah[cur][r*AST + c];     a[mi][1] = Ah[cur][(r+8)*AST + c];
                a[mi][2] = Ah[cur][r*AST + c + 4]; a[mi][3] = Ah[cur][(r+8)*AST + c + 4];
            }
            #pragma unroll
            for (int ni = 0; ni < 4; ni++) {
                int r = wn*32 + ni*8 + lr4, c = kb + lc4;
                uint32_t b0 = Bh[cur][r*AST + c], b1 = Bh[cur][r*AST + c + 4];
                mma8(acc[0][ni], a[0], b0, b1);
                mma8(acc[1][ni], a[1], b0, b1);
            }
        }

        if (more) store_tile(cur ^ 1, na1, na2, nbv);
        __syncthreads();
    }

    // epilogue
    #pragma unroll
    for (int mi = 0; mi < 2; mi++) {
        #pragma unroll
        for (int ni = 0; ni < 4; ni++) {
            int gm = m0 + wm*32 + mi*16 + lr4;
            int gn = n0 + wn*32 + ni*8 + 2*lc4;
            float b0 = bias[gn], b1 = bias[gn+1];
            float v00 = acc[mi][ni][0] + b0, v01 = acc[mi][ni][1] + b1;
            float v10 = acc[mi][ni][2] + b0, v11 = acc[mi][ni][3] + b1;
            if (MODE == 2) {
                const float* r0 = res + (size_t)gm * N + gn;
                const float* r1 = res + (size_t)(gm+8) * N + gn;
                v00 += r0[0]; v01 += r0[1]; v10 += r1[0]; v11 += r1[1];
            }
            *(float2*)(C + (size_t)gm * N + gn)     = make_float2(v00, v01);
            *(float2*)(C + (size_t)(gm+8) * N + gn) = make_float2(v10, v11);
        }
    }
}

// ---------------------------------------------------------------------------
// Repack qkv [M,768] -> g_Q/g_K/g_V [B,H,S,Dh] with RoPE applied to Q,K.
// qkv col = h*192 + d*3 + c ; pair (q0,k0,v0,q1,k1,v1) contiguous at h*192+6*d2
// ---------------------------------------------------------------------------
__global__ __launch_bounds__(256) void repack_rope_kernel(const float* __restrict__ kp)
{
    int idx = blockIdx.x * blockDim.x + threadIdx.x;   // B*H*S*32 pairs
    int d2 = idx & 31;
    int s  = (idx >> 5) & (SL - 1);
    int h  = (idx >> 16) & (HN - 1);
    int b  = idx >> 18;

    int gm = b * SL + s;
    const float* src = g_qkv + (size_t)gm * 768 + h * 192 + 6 * d2;
    float q0 = src[0], k0 = src[1], v0 = src[2];
    float q1 = src[3], k1 = src[4], v1 = src[5];

    const int SIN_OFF = BD * SL * DH;
    int kb = (b * SL + s) * DH + (d2 << 1);
    float c0 = kp[kb],           c1 = kp[kb + 1];
    float s0 = kp[SIN_OFF + kb], s1 = kp[SIN_OFF + kb + 1];

    int base = (((b * HN + h) * SL) + s) * DH + (d2 << 1);
    g_Q[base]     = q0 * c0 - q1 * s0;
    g_Q[base + 1] = q1 * c1 + q0 * s1;
    g_K[base]     = k0 * c0 - k1 * s0;
    g_K[base + 1] = k1 * c1 + k0 * s1;
    g_V[base]     = v0;
    g_V[base + 1] = v1;
}

// ---------------------------------------------------------------------------
// Flash attention, TF32 mma, max-free softmax.
// CTA: 64 queries x full key stream (64-key tiles). 8 warps: 4(M) x 2(N).
// Q fragments live in registers for the whole CTA. P overlays the K tile.
// ---------------------------------------------------------------------------
#define KST 68   // K/P smem stride
#define VST 72   // V smem stride
__global__ __launch_bounds__(256) void attn_kernel(float* __restrict__ ctx)
{
    __shared__ uint32_t KPs[64*KST];
    __shared__ uint32_t Vs[64*VST];
    __shared__ float lsum[2][64];

    const int t = threadIdx.x;
    const int w = t >> 5, wm = w & 3, wn = w >> 2;
    const int lane = t & 31, lr4 = lane >> 2, lc4 = lane & 3;
    const int bh = blockIdx.y;
    const int m0 = blockIdx.x << 6;

    const float* Qb = g_Q + (size_t)bh * SL * DH;
    const float* Kb = g_K + (size_t)bh * SL * DH;
    const float* Vb = g_V + (size_t)bh * SL * DH;
    const float scale = 0.125f;

    // Q fragments in registers (tf32, scale folded): 8 k-steps x 4 regs
    uint32_t qf[8][4];
    {
        int r = m0 + wm*16 + lr4;
        #pragma unroll
        for (int kk = 0; kk < 8; kk++) {
            int c = kk*8 + lc4;
            qf[kk][0] = f2tf_hi(Qb[(size_t)r     * DH + c]     * scale);
            qf[kk][1] = f2tf_hi(Qb[(size_t)(r+8) * DH + c]     * scale);
            qf[kk][2] = f2tf_hi(Qb[(size_t)r     * DH + c + 4] * scale);
            qf[kk][3] = f2tf_hi(Qb[(size_t)(r+8) * DH + c + 4] * scale);
        }
    }

    float o[4][4] = {};
    float l0 = 0.f, l1 = 0.f;

    const int ldr = t >> 2, ldc = (t & 3) << 2;   // loader: row, col base

    for (int n0 = 0; n0 < SL; n0 += 64) {
        __syncthreads();   // prev PV reads done
        #pragma unroll
        for (int c = 0; c < 4; c++) {
            int col = ldc + (c << 4);
            float4 kv = *(const float4*)(Kb + (size_t)(n0 + ldr) * DH + col);
            KPs[ldr*KST + col + 0] = f2tf_hi(kv.x);
            KPs[ldr*KST + col + 1] = f2tf_hi(kv.y);
            KPs[ldr*KST + col + 2] = f2tf_hi(kv.z);
            KPs[ldr*KST + col + 3] = f2tf_hi(kv.w);
            float4 vv = *(const float4*)(Vb + (size_t)(n0 + ldr) * DH + col);
            Vs[ldr*VST + col + 0] = f2tf_hi(vv.x);
            Vs[ldr*VST + col + 1] = f2tf_hi(vv.y);
            Vs[ldr*VST + col + 2] = f2tf_hi(vv.z);
            Vs[ldr*VST + col + 3] = f2tf_hi(vv.w);
        }
        __syncthreads();

        // S = Q K^T  (warp tile 16 x 32)
        float s[4][4] = {};
        #pragma unroll
        for (int kk = 0; kk < 8; kk++) {
            #pragma unroll
            for (int ni = 0; ni < 4; ni++) {
                int n = wn*32 + ni*8 + lr4;
                uint32_t b0 = KPs[n*KST + kk*8 + lc4];
                uint32_t b1 = KPs[n*KST + kk*8 + lc4 + 4];
                mma8(s[ni], qf[kk], b0, b1);
            }
        }

        // P = exp(S), partial row sums
        float rs0 = 0.f, rs1 = 0.f;
        #pragma unroll
        for (int ni = 0; ni < 4; ni++) {
            s[ni][0] = __expf(s[ni][0]); s[ni][1] = __expf(s[ni][1]);
            s[ni][2] = __expf(s[ni][2]); s[ni][3] = __expf(s[ni][3]);
            rs0 += s[ni][0] + s[ni][1];
            rs1 += s[ni][2] + s[ni][3];
        }
        rs0 += __shfl_xor_sync(0xffffffffu, rs0, 1);
        rs0 += __shfl_xor_sync(0xffffffffu, rs0, 2);
        rs1 += __shfl_xor_sync(0xffffffffu, rs1, 1);
        rs1 += __shfl_xor_sync(0xffffffffu, rs1, 2);
        l0 += rs0; l1 += rs1;

        __syncthreads();   // all warps done reading K tile
        {
            int pr = wm*16 + lr4;
            #pragma unroll
            for (int ni = 0; ni < 4; ni++) {
                int pc = wn*32 + ni*8 + 2*lc4;
                KPs[pr*KST + pc]     = f2tf_hi(s[ni][0]);
                KPs[pr*KST + pc + 1] = f2tf_hi(s[ni][1]);
                KPs[(pr+8)*KST + pc]     = f2tf_hi(s[ni][2]);
                KPs[(pr+8)*KST + pc + 1] = f2tf_hi(s[ni][3]);
            }
        }
        __syncthreads();

        // O += P V   (warp tile 16 x 32 over d)
        #pragma unroll
        for (int kk = 0; kk < 8; kk++) {
            int ar = wm*16 + lr4, ac = kk*8 + lc4;
            uint32_t a[4] = { KPs[ar*KST + ac], KPs[(ar+8)*KST + ac],
                              KPs[ar*KST + ac + 4], KPs[(ar+8)*KST + ac + 4] };
            #pragma unroll
            for (int ni = 0; ni < 4; ni++) {
                int vc = wn*32 + ni*8 + lr4;
                uint32_t b0 = Vs[(kk*8 + lc4)*VST + vc];
                uint32_t b1 = Vs[(kk*8 + lc4 + 4)*VST + vc];
                mma8(o[ni], a, b0, b1);
            }
        }
    }

    // combine row sums across the 2 N-warps
    {
        int pr = wm*16 + lr4;
        if (lc4 == 0) { lsum[wn][pr] = l0; lsum[wn][pr + 8] = l1; }
    }
    __syncthreads();
    {
        int pr = wm*16 + lr4;
        float inv0 = 1.0f / (lsum[0][pr]     + lsum[1][pr]);
        float inv1 = 1.0f / (lsum[0][pr + 8] + lsum[1][pr + 8]);
        const int b = bh >> 2, h = bh & 3;
        size_t r0 = (size_t)(b * SL + m0 + pr) * DM + h * DH;
        size_t r1 = r0 + 8 * DM;
        #pragma unroll
        for (int ni = 0; ni < 4; ni++) {
            int d = wn*32 + ni*8 + 2*lc4;
            *(float2*)(ctx + r0 + d) = make_float2(o[ni][0]*inv0, o[ni][1]*inv0);
            *(float2*)(ctx + r1 + d) = make_float2(o[ni][2]*inv1, o[ni][3]*inv1);
        }
    }
}

// ---------------------------------------------------------------------------
// LayerNorm (biased var) + exact GELU, in place on g_ff rows of 512
// ---------------------------------------------------------------------------
__global__ __launch_bounds__(256) void ln_gelu_kernel(const float* __restrict__ g,
                                                      const float* __restrict__ bb)
{
    int row = blockIdx.x;
    float* xr = g_ff + (size_t)row * 512;
    int t = threadIdx.x;
    float v0 = xr[t], v1 = xr[t + 256];
    float sum = v0 + v1;
    float sq  = v0 * v0 + v1 * v1;
    #pragma unroll
    for (int off = 16; off > 0; off >>= 1) {
        sum += __shfl_xor_sync(0xffffffffu, sum, off);
        sq  += __shfl_xor_sync(0xffffffffu, sq,  off);
    }
    __shared__ float ssum[8], ssq[8];
    __shared__ float smean, srstd;
    int w = t >> 5;
    if ((t & 31) == 0) { ssum[w] = sum; ssq[w] = sq; }
    __syncthreads();
    if (t == 0) {
        float S = 0.f, Q = 0.f;
        #pragma unroll
        for (int i = 0; i < 8; i++) { S += ssum[i]; Q += ssq[i]; }
        float mean = S * (1.0f / 512.0f);
        float var  = Q * (1.0f / 512.0f) - mean * mean;
        smean = mean;
        srstd = rsqrtf(var + 1e-5f);
    }
    __syncthreads();
    float mean = smean, rstd = srstd;

    float y0 = (v0 - mean) * rstd * g[t] + bb[t];
    float y1 = (v1 - mean) * rstd * g[t + 256] + bb[t + 256];
    xr[t]       = 0.5f * y0 * (1.0f + erff(y0 * 0.70710678118654752f));
    xr[t + 256] = 0.5f * y1 * (1.0f + erff(y1 * 0.70710678118654752f));
}

// ---------------------------------------------------------------------------
extern "C" void kernel_launch(void* const* d_in, const int* in_sizes, int n_in,
                              void* d_out, int out_size)
{
    (void)in_sizes; (void)n_in; (void)out_size;
    const float* desc   = (const float*)d_in[0];
    const float* kp     = (const float*)d_in[1];
    const float* Wqkv_w = (const float*)d_in[2];
    const float* Wqkv_b = (const float*)d_in[3];
    const float* Wo_w   = (const float*)d_in[4];
    const float* Wo_b   = (const float*)d_in[5];
    const float* W1_w   = (const float*)d_in[6];
    const float* W1_b   = (const float*)d_in[7];
    const float* ln_g   = (const float*)d_in[8];
    const float* ln_b   = (const float*)d_in[9];
    const float* W2_w   = (const float*)d_in[10];
    const float* W2_b   = (const float*)d_in[11];
    float* out = (float*)d_out;

    float *pqkv = nullptr, *pctx = nullptr, *pmsg = nullptr, *pff = nullptr;
    cudaGetSymbolAddress((void**)&pqkv, g_qkv);
    cudaGetSymbolAddress((void**)&pctx, g_ctx);
    cudaGetSymbolAddress((void**)&pmsg, g_msg);
    cudaGetSymbolAddress((void**)&pff,  g_ff);

    // 1. QKV projection
    gemm_tc<0, false><<<dim3(768 / 64, MR / 128), 256>>>(
        desc, nullptr, Wqkv_w, Wqkv_b, pqkv, nullptr, MR, 768, 256);

    // 2. Repack to [B,H,S,Dh] + RoPE
    repack_rope_kernel<<<(BD * HN * SL * 32) / 256, 256>>>(kp);

    // 3. Attention -> ctx [B,S,D]
    attn_kernel<<<dim3(SL / 64, BD * HN), 256>>>(pctx);

    // 4. message = ctx @ Wo^T + b
    gemm_tc<0, false><<<dim3(DM / 64, MR / 128), 256>>>(
        pctx, nullptr, Wo_w, Wo_b, pmsg, nullptr, MR, DM, DM);

    // 5. ff = concat(desc, msg) @ W1^T + b
    gemm_tc<0, true><<<dim3(512 / 64, MR / 128), 256>>>(
        desc, pmsg, W1_w, W1_b, pff, nullptr, MR, 512, 512);

    // 6. LayerNorm + GELU in place
    ln_gelu_kernel<<<MR, 256>>>(ln_g, ln_b);

    // 7. out = desc + ff @ W2^T + b
    gemm_tc<2, false><<<dim3(DM / 64, MR / 128), 256>>>(
        pff, nullptr, W2_w, W2_b, out, desc, MR, DM, 512);
}

// round 6
// speedup vs baseline: 4.2012x; 1.1293x over previous
#include <cuda_runtime.h>
#include <math.h>
#include <stdint.h>

#define BD 8
#define SL 2048
#define DM 256
#define HN 4
#define DH 64
#define MR (BD*SL)   // 16384

// Scratch (device globals; allocation-free per harness rules)
__device__ float g_qkv[MR*768];
__device__ float g_Q[BD*HN*SL*DH];
__device__ float g_K[BD*HN*SL*DH];
__device__ float g_V[BD*HN*SL*DH];
__device__ float g_ctx[MR*DM];
__device__ float g_msg[MR*DM];
__device__ float g_ff[MR*2*DM];

// ---- helpers ----------------------------------------------------------------
// NOTE: tf32 mma reads only the upper 19 bits of each 32-bit operand (HW
// truncation) -> we feed raw fp32 bits, no explicit conversion.
__device__ __forceinline__ void mma8(float* c, const uint32_t* a, uint32_t b0, uint32_t b1) {
    asm volatile(
        "mma.sync.aligned.m16n8k8.row.col.f32.tf32.tf32.f32 "
        "{%0,%1,%2,%3},{%4,%5,%6,%7},{%8,%9},{%0,%1,%2,%3};"
        : "+f"(c[0]), "+f"(c[1]), "+f"(c[2]), "+f"(c[3])
        : "r"(a[0]), "r"(a[1]), "r"(a[2]), "r"(a[3]), "r"(b0), "r"(b1));
}
__device__ __forceinline__ void cp16(uint32_t saddr, const void* gaddr) {
    asm volatile("cp.async.cg.shared.global [%0], [%1], 16;" :: "r"(saddr), "l"(gaddr));
}
__device__ __forceinline__ void cp_commit() { asm volatile("cp.async.commit_group;"); }
__device__ __forceinline__ void cp_wait_all() { asm volatile("cp.async.wait_group 0;"); }

// ---------------------------------------------------------------------------
// Tensor-core GEMM (TF32, cp.async 2-stage): C = A @ W^T + bias.
// A[M,K] rm, W[N,K] rm. BM=128, BN=128, BK=16.
// 256 threads = 8 warps (4 M x 2 N), warp tile 32x64.
// MODE 0: C = acc + bias;  MODE 2: C = acc + bias + res
// CONCAT: logical A = concat(A, A2) along K, both row stride 256
// ---------------------------------------------------------------------------
#define AST 20   // smem k-stride (16+4), conflict-free fragment loads
template<int MODE, bool CONCAT>
__global__ __launch_bounds__(256) void gemm_tc(
    const float* __restrict__ A, const float* __restrict__ A2,
    const float* __restrict__ W, const float* __restrict__ bias,
    float* __restrict__ C, const float* __restrict__ res,
    int M, int N, int K)
{
    __shared__ float As[2][128*AST], Bs[2][128*AST];
    const int t = threadIdx.x;
    const int w = t >> 5, wm = w & 3, wn = w >> 2;
    const int lane = t & 31, lr4 = lane >> 2, lc4 = lane & 3;
    const int m0 = blockIdx.y << 7, n0 = blockIdx.x << 7;

    float acc[2][8][4] = {};

    // loader mapping: each thread copies 2x16B for A, 2x16B for B
    const int ldr = t >> 1;              // row 0..127
    const int ldc = (t & 1) << 3;        // col base 0 or 8 (two float4s)

    uint32_t sA = (uint32_t)__cvta_generic_to_shared(&As[0][0]);
    uint32_t sB = (uint32_t)__cvta_generic_to_shared(&Bs[0][0]);
    const uint32_t stageA = 128*AST*4, stageB = 128*AST*4;

    auto issue_stage = [&](int k0, int buf) {
        int kk = k0 + ldc;
        const float* asrc;
        if (CONCAT) asrc = (kk >= 256) ? (A2 + (size_t)(m0 + ldr) * 256 + kk - 256)
                                       : (A  + (size_t)(m0 + ldr) * 256 + kk);
        else        asrc = A + (size_t)(m0 + ldr) * K + kk;
        uint32_t da = sA + buf*stageA + (ldr*AST + ldc)*4;
        cp16(da,      asrc);
        cp16(da + 16, asrc + 4);
        const float* bsrc = W + (size_t)(n0 + ldr) * K + k0 + ldc;
        uint32_t db = sB + buf*stageB + (ldr*AST + ldc)*4;
        cp16(db,      bsrc);
        cp16(db + 16, bsrc + 4);
        cp_commit();
    };

    issue_stage(0, 0);

    const int niters = K >> 4;
    for (int it = 0; it < niters; it++) {
        const int cur = it & 1;
        cp_wait_all();
        __syncthreads();
        if (it + 1 < niters) issue_stage((it + 1) << 4, cur ^ 1);   // overlaps mma

        const uint32_t* Ac = (const uint32_t*)As[cur];
        const uint32_t* Bc = (const uint32_t*)Bs[cur];
        #pragma unroll
        for (int ks = 0; ks < 2; ks++) {
            const int kb = ks << 3;
            uint32_t a[2][4];
            #pragma unroll
            for (int mi = 0; mi < 2; mi++) {
                int r = wm*32 + mi*16 + lr4, c = kb + lc4;
                a[mi][0] = Ac[r*AST + c];     a[mi][1] = Ac[(r+8)*AST + c];
                a[mi][2] = Ac[r*AST + c + 4]; a[mi][3] = Ac[(r+8)*AST + c + 4];
            }
            #pragma unroll
            for (int ni = 0; ni < 8; ni++) {
                int r = wn*64 + ni*8 + lr4, c = kb + lc4;
                uint32_t b0 = Bc[r*AST + c], b1 = Bc[r*AST + c + 4];
                mma8(acc[0][ni], a[0], b0, b1);
                mma8(acc[1][ni], a[1], b0, b1);
            }
        }
        __syncthreads();
    }

    // epilogue
    #pragma unroll
    for (int mi = 0; mi < 2; mi++) {
        #pragma unroll
        for (int ni = 0; ni < 8; ni++) {
            int gm = m0 + wm*32 + mi*16 + lr4;
            int gn = n0 + wn*64 + ni*8 + 2*lc4;
            float b0 = bias[gn], b1 = bias[gn+1];
            float v00 = acc[mi][ni][0] + b0, v01 = acc[mi][ni][1] + b1;
            float v10 = acc[mi][ni][2] + b0, v11 = acc[mi][ni][3] + b1;
            if (MODE == 2) {
                const float* r0 = res + (size_t)gm * N + gn;
                const float* r1 = res + (size_t)(gm+8) * N + gn;
                v00 += r0[0]; v01 += r0[1]; v10 += r1[0]; v11 += r1[1];
            }
            *(float2*)(C + (size_t)gm * N + gn)     = make_float2(v00, v01);
            *(float2*)(C + (size_t)(gm+8) * N + gn) = make_float2(v10, v11);
        }
    }
}

// ---------------------------------------------------------------------------
// Repack qkv [M,768] -> g_Q/g_K/g_V [B,H,S,Dh] with RoPE applied to Q,K.
// qkv col = h*192 + d*3 + c ; pair (q0,k0,v0,q1,k1,v1) contiguous at h*192+6*d2
// ---------------------------------------------------------------------------
__global__ __launch_bounds__(256) void repack_rope_kernel(const float* __restrict__ kp)
{
    int idx = blockIdx.x * blockDim.x + threadIdx.x;   // B*H*S*32 pairs
    int d2 = idx & 31;
    int s  = (idx >> 5) & (SL - 1);
    int h  = (idx >> 16) & (HN - 1);
    int b  = idx >> 18;

    int gm = b * SL + s;
    const float* src = g_qkv + (size_t)gm * 768 + h * 192 + 6 * d2;
    float q0 = src[0], k0 = src[1], v0 = src[2];
    float q1 = src[3], k1 = src[4], v1 = src[5];

    const int SIN_OFF = BD * SL * DH;
    int kb = (b * SL + s) * DH + (d2 << 1);
    float c0 = kp[kb],           c1 = kp[kb + 1];
    float s0 = kp[SIN_OFF + kb], s1 = kp[SIN_OFF + kb + 1];

    int base = (((b * HN + h) * SL) + s) * DH + (d2 << 1);
    g_Q[base]     = q0 * c0 - q1 * s0;
    g_Q[base + 1] = q1 * c1 + q0 * s1;
    g_K[base]     = k0 * c0 - k1 * s0;
    g_K[base + 1] = k1 * c1 + k0 * s1;
    g_V[base]     = v0;
    g_V[base + 1] = v1;
}

// ---------------------------------------------------------------------------
// Flash attention, TF32 mma, max-free softmax.
// CTA: 64 queries x full key stream (64-key tiles). 8 warps: 4(M) x 2(N).
// Q fragments live in registers for the whole CTA. P overlays the K tile.
// ---------------------------------------------------------------------------
#define KST 68   // K/P smem stride
#define VST 72   // V smem stride
__global__ __launch_bounds__(256) void attn_kernel(float* __restrict__ ctx)
{
    __shared__ uint32_t KPs[64*KST];
    __shared__ uint32_t Vs[64*VST];
    __shared__ float lsum[2][64];

    const int t = threadIdx.x;
    const int w = t >> 5, wm = w & 3, wn = w >> 2;
    const int lane = t & 31, lr4 = lane >> 2, lc4 = lane & 3;
    const int bh = blockIdx.y;
    const int m0 = blockIdx.x << 6;

    const float* Qb = g_Q + (size_t)bh * SL * DH;
    const float* Kb = g_K + (size_t)bh * SL * DH;
    const float* Vb = g_V + (size_t)bh * SL * DH;
    const float scale = 0.125f;

    // Q fragments in registers (scale folded): 8 k-steps x 4 regs
    uint32_t qf[8][4];
    {
        int r = m0 + wm*16 + lr4;
        #pragma unroll
        for (int kk = 0; kk < 8; kk++) {
            int c = kk*8 + lc4;
            qf[kk][0] = __float_as_uint(Qb[(size_t)r     * DH + c]     * scale);
            qf[kk][1] = __float_as_uint(Qb[(size_t)(r+8) * DH + c]     * scale);
            qf[kk][2] = __float_as_uint(Qb[(size_t)r     * DH + c + 4] * scale);
            qf[kk][3] = __float_as_uint(Qb[(size_t)(r+8) * DH + c + 4] * scale);
        }
    }

    float o[4][4] = {};
    float l0 = 0.f, l1 = 0.f;

    const int ldr = t >> 2, ldc = (t & 3) << 2;   // loader: row, col base

    for (int n0 = 0; n0 < SL; n0 += 64) {
        __syncthreads();   // prev PV reads done
        #pragma unroll
        for (int c = 0; c < 4; c++) {
            int col = ldc + (c << 4);
            float4 kv = *(const float4*)(Kb + (size_t)(n0 + ldr) * DH + col);
            *(uint4*)&KPs[ldr*KST + col] = *(const uint4*)&kv;
            float4 vv = *(const float4*)(Vb + (size_t)(n0 + ldr) * DH + col);
            *(uint4*)&Vs[ldr*VST + col] = *(const uint4*)&vv;
        }
        __syncthreads();

        // S = Q K^T  (warp tile 16 x 32)
        float s[4][4] = {};
        #pragma unroll
        for (int kk = 0; kk < 8; kk++) {
            #pragma unroll
            for (int ni = 0; ni < 4; ni++) {
                int n = wn*32 + ni*8 + lr4;
                uint32_t b0 = KPs[n*KST + kk*8 + lc4];
                uint32_t b1 = KPs[n*KST + kk*8 + lc4 + 4];
                mma8(s[ni], qf[kk], b0, b1);
            }
        }

        // P = exp(S), partial row sums
        float rs0 = 0.f, rs1 = 0.f;
        #pragma unroll
        for (int ni = 0; ni < 4; ni++) {
            s[ni][0] = __expf(s[ni][0]); s[ni][1] = __expf(s[ni][1]);
            s[ni][2] = __expf(s[ni][2]); s[ni][3] = __expf(s[ni][3]);
            rs0 += s[ni][0] + s[ni][1];
            rs1 += s[ni][2] + s[ni][3];
        }
        rs0 += __shfl_xor_sync(0xffffffffu, rs0, 1);
        rs0 += __shfl_xor_sync(0xffffffffu, rs0, 2);
        rs1 += __shfl_xor_sync(0xffffffffu, rs1, 1);
        rs1 += __shfl_xor_sync(0xffffffffu, rs1, 2);
        l0 += rs0; l1 += rs1;

        __syncthreads();   // all warps done reading K tile
        {
            int pr = wm*16 + lr4;
            #pragma unroll
            for (int ni = 0; ni < 4; ni++) {
                int pc = wn*32 + ni*8 + 2*lc4;
                KPs[pr*KST + pc]     = __float_as_uint(s[ni][0]);
                KPs[pr*KST + pc + 1] = __float_as_uint(s[ni][1]);
                KPs[(pr+8)*KST + pc]     = __float_as_uint(s[ni][2]);
                KPs[(pr+8)*KST + pc + 1] = __float_as_uint(s[ni][3]);
            }
        }
        __syncthreads();

        // O += P V   (warp tile 16 x 32 over d)
        #pragma unroll
        for (int kk = 0; kk < 8; kk++) {
            int ar = wm*16 + lr4, ac = kk*8 + lc4;
            uint32_t a[4] = { KPs[ar*KST + ac], KPs[(ar+8)*KST + ac],
                              KPs[ar*KST + ac + 4], KPs[(ar+8)*KST + ac + 4] };
            #pragma unroll
            for (int ni = 0; ni < 4; ni++) {
                int vc = wn*32 + ni*8 + lr4;
                uint32_t b0 = Vs[(kk*8 + lc4)*VST + vc];
                uint32_t b1 = Vs[(kk*8 + lc4 + 4)*VST + vc];
                mma8(o[ni], a, b0, b1);
            }
        }
    }

    // combine row sums across the 2 N-warps
    {
        int pr = wm*16 + lr4;
        if (lc4 == 0) { lsum[wn][pr] = l0; lsum[wn][pr + 8] = l1; }
    }
    __syncthreads();
    {
        int pr = wm*16 + lr4;
        float inv0 = 1.0f / (lsum[0][pr]     + lsum[1][pr]);
        float inv1 = 1.0f / (lsum[0][pr + 8] + lsum[1][pr + 8]);
        const int b = bh >> 2, h = bh & 3;
        size_t r0 = (size_t)(b * SL + m0 + pr) * DM + h * DH;
        size_t r1 = r0 + 8 * DM;
        #pragma unroll
        for (int ni = 0; ni < 4; ni++) {
            int d = wn*32 + ni*8 + 2*lc4;
            *(float2*)(ctx + r0 + d) = make_float2(o[ni][0]*inv0, o[ni][1]*inv0);
            *(float2*)(ctx + r1 + d) = make_float2(o[ni][2]*inv1, o[ni][3]*inv1);
        }
    }
}

// ---------------------------------------------------------------------------
// LayerNorm (biased var) + exact GELU, in place on g_ff rows of 512
// ---------------------------------------------------------------------------
__global__ __launch_bounds__(256) void ln_gelu_kernel(const float* __restrict__ g,
                                                      const float* __restrict__ bb)
{
    int row = blockIdx.x;
    float* xr = g_ff + (size_t)row * 512;
    int t = threadIdx.x;
    float v0 = xr[t], v1 = xr[t + 256];
    float sum = v0 + v1;
    float sq  = v0 * v0 + v1 * v1;
    #pragma unroll
    for (int off = 16; off > 0; off >>= 1) {
        sum += __shfl_xor_sync(0xffffffffu, sum, off);
        sq  += __shfl_xor_sync(0xffffffffu, sq,  off);
    }
    __shared__ float ssum[8], ssq[8];
    __shared__ float smean, srstd;
    int w = t >> 5;
    if ((t & 31) == 0) { ssum[w] = sum; ssq[w] = sq; }
    __syncthreads();
    if (t == 0) {
        float S = 0.f, Q = 0.f;
        #pragma unroll
        for (int i = 0; i < 8; i++) { S += ssum[i]; Q += ssq[i]; }
        float mean = S * (1.0f / 512.0f);
        float var  = Q * (1.0f / 512.0f) - mean * mean;
        smean = mean;
        srstd = rsqrtf(var + 1e-5f);
    }
    __syncthreads();
    float mean = smean, rstd = srstd;

    float y0 = (v0 - mean) * rstd * g[t] + bb[t];
    float y1 = (v1 - mean) * rstd * g[t + 256] + bb[t + 256];
    xr[t]       = 0.5f * y0 * (1.0f + erff(y0 * 0.70710678118654752f));
    xr[t + 256] = 0.5f * y1 * (1.0f + erff(y1 * 0.70710678118654752f));
}

// ---------------------------------------------------------------------------
extern "C" void kernel_launch(void* const* d_in, const int* in_sizes, int n_in,
                              void* d_out, int out_size)
{
    (void)in_sizes; (void)n_in; (void)out_size;
    const float* desc   = (const float*)d_in[0];
    const float* kp     = (const float*)d_in[1];
    const float* Wqkv_w = (const float*)d_in[2];
    const float* Wqkv_b = (const float*)d_in[3];
    const float* Wo_w   = (const float*)d_in[4];
    const float* Wo_b   = (const float*)d_in[5];
    const float* W1_w   = (const float*)d_in[6];
    const float* W1_b   = (const float*)d_in[7];
    const float* ln_g   = (const float*)d_in[8];
    const float* ln_b   = (const float*)d_in[9];
    const float* W2_w   = (const float*)d_in[10];
    const float* W2_b   = (const float*)d_in[11];
    float* out = (float*)d_out;

    float *pqkv = nullptr, *pctx = nullptr, *pmsg = nullptr, *pff = nullptr;
    cudaGetSymbolAddress((void**)&pqkv, g_qkv);
    cudaGetSymbolAddress((void**)&pctx, g_ctx);
    cudaGetSymbolAddress((void**)&pmsg, g_msg);
    cudaGetSymbolAddress((void**)&pff,  g_ff);

    // 1. QKV projection
    gemm_tc<0, false><<<dim3(768 / 128, MR / 128), 256>>>(
        desc, nullptr, Wqkv_w, Wqkv_b, pqkv, nullptr, MR, 768, 256);

    // 2. Repack to [B,H,S,Dh] + RoPE
    repack_rope_kernel<<<(BD * HN * SL * 32) / 256, 256>>>(kp);

    // 3. Attention -> ctx [B,S,D]
    attn_kernel<<<dim3(SL / 64, BD * HN), 256>>>(pctx);

    // 4. message = ctx @ Wo^T + b
    gemm_tc<0, false><<<dim3(DM / 128, MR / 128), 256>>>(
        pctx, nullptr, Wo_w, Wo_b, pmsg, nullptr, MR, DM, DM);

    // 5. ff = concat(desc, msg) @ W1^T + b
    gemm_tc<0, true><<<dim3(512 / 128, MR / 128), 256>>>(
        desc, pmsg, W1_w, W1_b, pff, nullptr, MR, 512, 512);

    // 6. LayerNorm + GELU in place
    ln_gelu_kernel<<<MR, 256>>>(ln_g, ln_b);

    // 7. out = desc + ff @ W2^T + b
    gemm_tc<2, false><<<dim3(DM / 128, MR / 128), 256>>>(
        pff, nullptr, W2_w, W2_b, out, desc, MR, DM, 512);
}

// round 7
// speedup vs baseline: 6.3365x; 1.5083x over previous
#include <cuda_runtime.h>
#include <cuda_bf16.h>
#include <math.h>
#include <stdint.h>

#define BD 8
#define SL 2048
#define DM 256
#define HN 4
#define DH 64
#define MR (BD*SL)   // 16384

// Scratch (device globals; allocation-free per harness rules)
__device__ float g_qkv[MR*768];
__device__ __nv_bfloat16 g_Qh[BD*HN*SL*DH];   // roped, pre-scaled
__device__ __nv_bfloat16 g_Kh[BD*HN*SL*DH];   // roped
__device__ __nv_bfloat16 g_Vr[BD*HN*SL*DH];   // row-major [s][d]
__device__ __nv_bfloat16 g_Vt[BD*HN*DH*SL];   // transposed [d][s]
__device__ float g_ctx[MR*DM];
__device__ float g_msg[MR*DM];
__device__ float g_ff[MR*2*DM];

// ---- helpers ----------------------------------------------------------------
__device__ __forceinline__ void mma8(float* c, const uint32_t* a, uint32_t b0, uint32_t b1) {
    asm volatile(
        "mma.sync.aligned.m16n8k8.row.col.f32.tf32.tf32.f32 "
        "{%0,%1,%2,%3},{%4,%5,%6,%7},{%8,%9},{%0,%1,%2,%3};"
        : "+f"(c[0]), "+f"(c[1]), "+f"(c[2]), "+f"(c[3])
        : "r"(a[0]), "r"(a[1]), "r"(a[2]), "r"(a[3]), "r"(b0), "r"(b1));
}
__device__ __forceinline__ void mma16(float* c, const uint32_t* a, uint32_t b0, uint32_t b1) {
    asm volatile(
        "mma.sync.aligned.m16n8k16.row.col.f32.bf16.bf16.f32 "
        "{%0,%1,%2,%3},{%4,%5,%6,%7},{%8,%9},{%0,%1,%2,%3};"
        : "+f"(c[0]), "+f"(c[1]), "+f"(c[2]), "+f"(c[3])
        : "r"(a[0]), "r"(a[1]), "r"(a[2]), "r"(a[3]), "r"(b0), "r"(b1));
}
__device__ __forceinline__ void cp16(uint32_t saddr, const void* gaddr) {
    asm volatile("cp.async.cg.shared.global [%0], [%1], 16;" :: "r"(saddr), "l"(gaddr));
}
__device__ __forceinline__ void cp_commit() { asm volatile("cp.async.commit_group;"); }
__device__ __forceinline__ void cp_wait_all() { asm volatile("cp.async.wait_group 0;"); }
__device__ __forceinline__ uint32_t packbf(float a, float b) {
    __nv_bfloat162 h = __floats2bfloat162_rn(a, b);
    return *(uint32_t*)&h;
}

// ---------------------------------------------------------------------------
// Tensor-core GEMM (TF32, cp.async 2-stage): C = A @ W^T + bias.
// BM=128, BN=128, BK=16. 8 warps (4M x 2N), warp tile 32x64.
// ---------------------------------------------------------------------------
#define AST 20
template<int MODE, bool CONCAT>
__global__ __launch_bounds__(256) void gemm_tc(
    const float* __restrict__ A, const float* __restrict__ A2,
    const float* __restrict__ W, const float* __restrict__ bias,
    float* __restrict__ C, const float* __restrict__ res,
    int M, int N, int K)
{
    __shared__ float As[2][128*AST], Bs[2][128*AST];
    const int t = threadIdx.x;
    const int w = t >> 5, wm = w & 3, wn = w >> 2;
    const int lane = t & 31, lr4 = lane >> 2, lc4 = lane & 3;
    const int m0 = blockIdx.y << 7, n0 = blockIdx.x << 7;

    float acc[2][8][4] = {};

    const int ldr = t >> 1;
    const int ldc = (t & 1) << 3;

    uint32_t sA = (uint32_t)__cvta_generic_to_shared(&As[0][0]);
    uint32_t sB = (uint32_t)__cvta_generic_to_shared(&Bs[0][0]);
    const uint32_t stageA = 128*AST*4, stageB = 128*AST*4;

    auto issue_stage = [&](int k0, int buf) {
        int kk = k0 + ldc;
        const float* asrc;
        if (CONCAT) asrc = (kk >= 256) ? (A2 + (size_t)(m0 + ldr) * 256 + kk - 256)
                                       : (A  + (size_t)(m0 + ldr) * 256 + kk);
        else        asrc = A + (size_t)(m0 + ldr) * K + kk;
        uint32_t da = sA + buf*stageA + (ldr*AST + ldc)*4;
        cp16(da,      asrc);
        cp16(da + 16, asrc + 4);
        const float* bsrc = W + (size_t)(n0 + ldr) * K + k0 + ldc;
        uint32_t db = sB + buf*stageB + (ldr*AST + ldc)*4;
        cp16(db,      bsrc);
        cp16(db + 16, bsrc + 4);
        cp_commit();
    };

    issue_stage(0, 0);

    const int niters = K >> 4;
    for (int it = 0; it < niters; it++) {
        const int cur = it & 1;
        cp_wait_all();
        __syncthreads();
        if (it + 1 < niters) issue_stage((it + 1) << 4, cur ^ 1);

        const uint32_t* Ac = (const uint32_t*)As[cur];
        const uint32_t* Bc = (const uint32_t*)Bs[cur];
        #pragma unroll
        for (int ks = 0; ks < 2; ks++) {
            const int kb = ks << 3;
            uint32_t a[2][4];
            #pragma unroll
            for (int mi = 0; mi < 2; mi++) {
                int r = wm*32 + mi*16 + lr4, c = kb + lc4;
                a[mi][0] = Ac[r*AST + c];     a[mi][1] = Ac[(r+8)*AST + c];
                a[mi][2] = Ac[r*AST + c + 4]; a[mi][3] = Ac[(r+8)*AST + c + 4];
            }
            #pragma unroll
            for (int ni = 0; ni < 8; ni++) {
                int r = wn*64 + ni*8 + lr4, c = kb + lc4;
                uint32_t b0 = Bc[r*AST + c], b1 = Bc[r*AST + c + 4];
                mma8(acc[0][ni], a[0], b0, b1);
                mma8(acc[1][ni], a[1], b0, b1);
            }
        }
        __syncthreads();
    }

    #pragma unroll
    for (int mi = 0; mi < 2; mi++) {
        #pragma unroll
        for (int ni = 0; ni < 8; ni++) {
            int gm = m0 + wm*32 + mi*16 + lr4;
            int gn = n0 + wn*64 + ni*8 + 2*lc4;
            float b0 = bias[gn], b1 = bias[gn+1];
            float v00 = acc[mi][ni][0] + b0, v01 = acc[mi][ni][1] + b1;
            float v10 = acc[mi][ni][2] + b0, v11 = acc[mi][ni][3] + b1;
            if (MODE == 2) {
                const float* r0 = res + (size_t)gm * N + gn;
                const float* r1 = res + (size_t)(gm+8) * N + gn;
                v00 += r0[0]; v01 += r0[1]; v10 += r1[0]; v11 += r1[1];
            }
            *(float2*)(C + (size_t)gm * N + gn)     = make_float2(v00, v01);
            *(float2*)(C + (size_t)(gm+8) * N + gn) = make_float2(v10, v11);
        }
    }
}

// ---------------------------------------------------------------------------
// Repack qkv [M,768] -> bf16 Q (roped+scaled), K (roped), V row-major.
// qkv col = h*192 + d*3 + c ; pair (q0,k0,v0,q1,k1,v1) contiguous at h*192+6*d2
// ---------------------------------------------------------------------------
__global__ __launch_bounds__(256) void repack_rope_kernel(const float* __restrict__ kp)
{
    int idx = blockIdx.x * blockDim.x + threadIdx.x;   // B*H*S*32 pairs
    int d2 = idx & 31;
    int s  = (idx >> 5) & (SL - 1);
    int h  = (idx >> 16) & (HN - 1);
    int b  = idx >> 18;

    int gm = b * SL + s;
    const float* src = g_qkv + (size_t)gm * 768 + h * 192 + 6 * d2;
    float q0 = src[0], k0 = src[1], v0 = src[2];
    float q1 = src[3], k1 = src[4], v1 = src[5];

    const int SIN_OFF = BD * SL * DH;
    int kb = (b * SL + s) * DH + (d2 << 1);
    float c0 = kp[kb],           c1 = kp[kb + 1];
    float s0 = kp[SIN_OFF + kb], s1 = kp[SIN_OFF + kb + 1];

    int base = (((b * HN + h) * SL) + s) * DH + (d2 << 1);
    const float scale = 0.125f;
    *(__nv_bfloat162*)&g_Qh[base] =
        __floats2bfloat162_rn((q0*c0 - q1*s0)*scale, (q1*c1 + q0*s1)*scale);
    *(__nv_bfloat162*)&g_Kh[base] =
        __floats2bfloat162_rn(k0*c0 - k1*s0, k1*c1 + k0*s1);
    *(__nv_bfloat162*)&g_Vr[base] = __floats2bfloat162_rn(v0, v1);
}

// ---------------------------------------------------------------------------
// V transpose: g_Vr [bh][s][d] -> g_Vt [bh][d][s], 64x64 smem tiles
// ---------------------------------------------------------------------------
__global__ __launch_bounds__(256) void vtrans_kernel()
{
    __shared__ uint32_t tile[64*33];   // [s][d-pair], stride 33 words
    const int t = threadIdx.x;
    const int bh = blockIdx.y;
    const int s0 = blockIdx.x << 6;

    // load: 64 rows x 32 words; thread: row t>>2, words (t&3)*8 .. +8
    {
        int sr = t >> 2, wc = (t & 3) * 8;
        const uint32_t* src = (const uint32_t*)(g_Vr + (size_t)bh*SL*DH + (size_t)(s0+sr)*DH) + wc;
        #pragma unroll
        for (int i = 0; i < 8; i++) tile[sr*33 + wc + i] = src[i];
    }
    __syncthreads();
    // write: thread: d = t>>2, s-chunk (t&3)*16
    {
        int d = t >> 2, sc = (t & 3) * 16;
        uint32_t outw[8];
        #pragma unroll
        for (int j = 0; j < 8; j++) {
            uint32_t w0 = tile[(sc + 2*j    )*33 + (d >> 1)];
            uint32_t w1 = tile[(sc + 2*j + 1)*33 + (d >> 1)];
            uint32_t lo = (d & 1) ? (w0 >> 16) : (w0 & 0xffffu);
            uint32_t hi = (d & 1) ? (w1 >> 16) : (w1 & 0xffffu);
            outw[j] = lo | (hi << 16);
        }
        uint32_t* dst = (uint32_t*)(g_Vt + (size_t)bh*DH*SL + (size_t)d*SL + s0 + sc);
        *(uint4*)dst       = make_uint4(outw[0], outw[1], outw[2], outw[3]);
        *(uint4*)(dst + 4) = make_uint4(outw[4], outw[5], outw[6], outw[7]);
    }
}

// ---------------------------------------------------------------------------
// Flash attention, bf16 m16n8k16, max-free softmax, cp.async 2-stage K/V.
// CTA: 64 queries x key stream in 64-key tiles. 8 warps: 4(M) x 2(N).
// ---------------------------------------------------------------------------
#define KW 36   // smem row stride in 4B words (72 bf16)
__global__ __launch_bounds__(256) void attn_kernel(float* __restrict__ ctx)
{
    __shared__ uint32_t Ks[2][64*KW];
    __shared__ uint32_t Vts[2][64*KW];
    __shared__ uint32_t Ps[64*KW];
    __shared__ float lsum[2][64];

    const int t = threadIdx.x;
    const int w = t >> 5, wm = w & 3, wn = w >> 2;
    const int lane = t & 31, g = lane >> 2, tg = lane & 3;
    const int bh = blockIdx.y;
    const int m0 = blockIdx.x << 6;

    const __nv_bfloat16* Qb  = g_Qh + (size_t)bh * SL * DH;
    const __nv_bfloat16* Kb  = g_Kh + (size_t)bh * SL * DH;
    const __nv_bfloat16* Vtb = g_Vt + (size_t)bh * DH * SL;

    // Q fragments in registers: 4 k-steps x 4 regs (bf16 pairs)
    uint32_t qf[4][4];
    {
        const uint32_t* Qw = (const uint32_t*)Qb;   // 32 words per row
        int r = m0 + wm*16 + g;
        #pragma unroll
        for (int kk = 0; kk < 4; kk++) {
            qf[kk][0] = Qw[(size_t)r    *32 + kk*8 + tg];
            qf[kk][1] = Qw[(size_t)(r+8)*32 + kk*8 + tg];
            qf[kk][2] = Qw[(size_t)r    *32 + kk*8 + tg + 4];
            qf[kk][3] = Qw[(size_t)(r+8)*32 + kk*8 + tg + 4];
        }
    }

    const int ldrow = t >> 2, lb = (t & 3) * 32;   // row, byte offset in 128B row
    uint32_t sK = (uint32_t)__cvta_generic_to_shared(&Ks[0][0]);
    uint32_t sV = (uint32_t)__cvta_generic_to_shared(&Vts[0][0]);
    const uint32_t stage = 64*KW*4;

    auto issue_kv = [&](int n0, int buf) {
        const char* kg = (const char*)(Kb + (size_t)(n0 + ldrow) * DH) + lb;
        uint32_t dk = sK + buf*stage + ldrow*144 + lb;
        cp16(dk, kg); cp16(dk + 16, kg + 16);
        const char* vg = (const char*)(Vtb + (size_t)ldrow * SL + n0) + lb;
        uint32_t dv = sV + buf*stage + ldrow*144 + lb;
        cp16(dv, vg); cp16(dv + 16, vg + 16);
        cp_commit();
    };

    issue_kv(0, 0);

    float o[4][4] = {};
    float l0 = 0.f, l1 = 0.f;

    for (int n0 = 0; n0 < SL; n0 += 64) {
        const int cur = (n0 >> 6) & 1;
        cp_wait_all();
        __syncthreads();   // K/V ready; prev-iter PV reads of Ps done
        if (n0 + 64 < SL) issue_kv(n0 + 64, cur ^ 1);

        // S = Q K^T  (warp tile 16 x 32)
        float s[4][4] = {};
        #pragma unroll
        for (int kk = 0; kk < 4; kk++) {
            #pragma unroll
            for (int ni = 0; ni < 4; ni++) {
                int kr = wn*32 + ni*8 + g;
                uint32_t b0 = Ks[cur][kr*KW + kk*8 + tg];
                uint32_t b1 = Ks[cur][kr*KW + kk*8 + tg + 4];
                mma16(s[ni], qf[kk], b0, b1);
            }
        }

        // P = exp(S), partial row sums
        float rs0 = 0.f, rs1 = 0.f;
        #pragma unroll
        for (int ni = 0; ni < 4; ni++) {
            s[ni][0] = __expf(s[ni][0]); s[ni][1] = __expf(s[ni][1]);
            s[ni][2] = __expf(s[ni][2]); s[ni][3] = __expf(s[ni][3]);
            rs0 += s[ni][0] + s[ni][1];
            rs1 += s[ni][2] + s[ni][3];
        }
        rs0 += __shfl_xor_sync(0xffffffffu, rs0, 1);
        rs0 += __shfl_xor_sync(0xffffffffu, rs0, 2);
        rs1 += __shfl_xor_sync(0xffffffffu, rs1, 1);
        rs1 += __shfl_xor_sync(0xffffffffu, rs1, 2);
        l0 += rs0; l1 += rs1;

        // store P (bf16 pairs, natural accumulator layout)
        {
            int pr = wm*16 + g;
            #pragma unroll
            for (int ni = 0; ni < 4; ni++) {
                int pw = wn*16 + ni*4 + tg;
                Ps[pr*KW + pw]     = packbf(s[ni][0], s[ni][1]);
                Ps[(pr+8)*KW + pw] = packbf(s[ni][2], s[ni][3]);
            }
        }
        __syncthreads();

        // O += P V  (warp tile 16 x 32 over d)
        #pragma unroll
        for (int kk = 0; kk < 4; kk++) {
            int ar = wm*16 + g;
            uint32_t a[4] = { Ps[ar*KW + kk*8 + tg],     Ps[(ar+8)*KW + kk*8 + tg],
                              Ps[ar*KW + kk*8 + tg + 4], Ps[(ar+8)*KW + kk*8 + tg + 4] };
            #pragma unroll
            for (int ni = 0; ni < 4; ni++) {
                int vr = wn*32 + ni*8 + g;
                uint32_t b0 = Vts[cur][vr*KW + kk*8 + tg];
                uint32_t b1 = Vts[cur][vr*KW + kk*8 + tg + 4];
                mma16(o[ni], a, b0, b1);
            }
        }
    }

    // combine row sums across the 2 N-warps
    {
        int pr = wm*16 + g;
        if (tg == 0) { lsum[wn][pr] = l0; lsum[wn][pr + 8] = l1; }
    }
    __syncthreads();
    {
        int pr = wm*16 + g;
        float inv0 = 1.0f / (lsum[0][pr]     + lsum[1][pr]);
        float inv1 = 1.0f / (lsum[0][pr + 8] + lsum[1][pr + 8]);
        const int b = bh >> 2, h = bh & 3;
        size_t r0 = (size_t)(b * SL + m0 + pr) * DM + h * DH;
        size_t r1 = r0 + 8 * DM;
        #pragma unroll
        for (int ni = 0; ni < 4; ni++) {
            int d = wn*32 + ni*8 + 2*tg;
            *(float2*)(ctx + r0 + d) = make_float2(o[ni][0]*inv0, o[ni][1]*inv0);
            *(float2*)(ctx + r1 + d) = make_float2(o[ni][2]*inv1, o[ni][3]*inv1);
        }
    }
}

// ---------------------------------------------------------------------------
// LayerNorm (biased var) + exact GELU, in place on g_ff rows of 512
// ---------------------------------------------------------------------------
__global__ __launch_bounds__(256) void ln_gelu_kernel(const float* __restrict__ g,
                                                      const float* __restrict__ bb)
{
    int row = blockIdx.x;
    float* xr = g_ff + (size_t)row * 512;
    int t = threadIdx.x;
    float v0 = xr[t], v1 = xr[t + 256];
    float sum = v0 + v1;
    float sq  = v0 * v0 + v1 * v1;
    #pragma unroll
    for (int off = 16; off > 0; off >>= 1) {
        sum += __shfl_xor_sync(0xffffffffu, sum, off);
        sq  += __shfl_xor_sync(0xffffffffu, sq,  off);
    }
    __shared__ float ssum[8], ssq[8];
    __shared__ float smean, srstd;
    int w = t >> 5;
    if ((t & 31) == 0) { ssum[w] = sum; ssq[w] = sq; }
    __syncthreads();
    if (t == 0) {
        float S = 0.f, Q = 0.f;
        #pragma unroll
        for (int i = 0; i < 8; i++) { S += ssum[i]; Q += ssq[i]; }
        float mean = S * (1.0f / 512.0f);
        float var  = Q * (1.0f / 512.0f) - mean * mean;
        smean = mean;
        srstd = rsqrtf(var + 1e-5f);
    }
    __syncthreads();
    float mean = smean, rstd = srstd;

    float y0 = (v0 - mean) * rstd * g[t] + bb[t];
    float y1 = (v1 - mean) * rstd * g[t + 256] + bb[t + 256];
    xr[t]       = 0.5f * y0 * (1.0f + erff(y0 * 0.70710678118654752f));
    xr[t + 256] = 0.5f * y1 * (1.0f + erff(y1 * 0.70710678118654752f));
}

// ---------------------------------------------------------------------------
extern "C" void kernel_launch(void* const* d_in, const int* in_sizes, int n_in,
                              void* d_out, int out_size)
{
    (void)in_sizes; (void)n_in; (void)out_size;
    const float* desc   = (const float*)d_in[0];
    const float* kp     = (const float*)d_in[1];
    const float* Wqkv_w = (const float*)d_in[2];
    const float* Wqkv_b = (const float*)d_in[3];
    const float* Wo_w   = (const float*)d_in[4];
    const float* Wo_b   = (const float*)d_in[5];
    const float* W1_w   = (const float*)d_in[6];
    const float* W1_b   = (const float*)d_in[7];
    const float* ln_g   = (const float*)d_in[8];
    const float* ln_b   = (const float*)d_in[9];
    const float* W2_w   = (const float*)d_in[10];
    const float* W2_b   = (const float*)d_in[11];
    float* out = (float*)d_out;

    float *pqkv = nullptr, *pctx = nullptr, *pmsg = nullptr, *pff = nullptr;
    cudaGetSymbolAddress((void**)&pqkv, g_qkv);
    cudaGetSymbolAddress((void**)&pctx, g_ctx);
    cudaGetSymbolAddress((void**)&pmsg, g_msg);
    cudaGetSymbolAddress((void**)&pff,  g_ff);

    // 1. QKV projection
    gemm_tc<0, false><<<dim3(768 / 128, MR / 128), 256>>>(
        desc, nullptr, Wqkv_w, Wqkv_b, pqkv, nullptr, MR, 768, 256);

    // 2. Repack to bf16 [B,H,S,Dh] + RoPE (+scale on Q)
    repack_rope_kernel<<<(BD * HN * SL * 32) / 256, 256>>>(kp);

    // 2b. V transpose -> [B,H,Dh,S]
    vtrans_kernel<<<dim3(SL / 64, BD * HN), 256>>>();

    // 3. Attention -> ctx [B,S,D]
    attn_kernel<<<dim3(SL / 64, BD * HN), 256>>>(pctx);

    // 4. message = ctx @ Wo^T + b
    gemm_tc<0, false><<<dim3(DM / 128, MR / 128), 256>>>(
        pctx, nullptr, Wo_w, Wo_b, pmsg, nullptr, MR, DM, DM);

    // 5. ff = concat(desc, msg) @ W1^T + b
    gemm_tc<0, true><<<dim3(512 / 128, MR / 128), 256>>>(
        desc, pmsg, W1_w, W1_b, pff, nullptr, MR, 512, 512);

    // 6. LayerNorm + GELU in place
    ln_gelu_kernel<<<MR, 256>>>(ln_g, ln_b);

    // 7. out = desc + ff @ W2^T + b
    gemm_tc<2, false><<<dim3(DM / 128, MR / 128), 256>>>(
        pff, nullptr, W2_w, W2_b, out, desc, MR, DM, 512);
}

// round 10
// speedup vs baseline: 6.4698x; 1.0210x over previous
#include <cuda_runtime.h>
#include <cuda_bf16.h>
#include <math.h>
#include <stdint.h>

#define BD 8
#define SL 2048
#define DM 256
#define HN 4
#define DH 64
#define MR (BD*SL)   // 16384

// Scratch (device globals; allocation-free per harness rules)
__device__ float g_qkv[MR*768];
__device__ __nv_bfloat16 g_Qh[BD*HN*SL*DH];   // roped, pre-scaled by 0.125*log2(e)
__device__ __nv_bfloat16 g_Kh[BD*HN*SL*DH];   // roped
__device__ __nv_bfloat16 g_Vr[BD*HN*SL*DH];   // row-major [s][d]
__device__ __nv_bfloat16 g_Vt[BD*HN*DH*SL];   // transposed [d][s]
__device__ float g_ctx[MR*DM];
__device__ float g_msg[MR*DM];
__device__ float g_ff[MR*2*DM];

// ---- helpers ----------------------------------------------------------------
__device__ __forceinline__ void mma8(float* c, const uint32_t* a, uint32_t b0, uint32_t b1) {
    asm volatile(
        "mma.sync.aligned.m16n8k8.row.col.f32.tf32.tf32.f32 "
        "{%0,%1,%2,%3},{%4,%5,%6,%7},{%8,%9},{%0,%1,%2,%3};"
        : "+f"(c[0]), "+f"(c[1]), "+f"(c[2]), "+f"(c[3])
        : "r"(a[0]), "r"(a[1]), "r"(a[2]), "r"(a[3]), "r"(b0), "r"(b1));
}
__device__ __forceinline__ void mma16(float* c, const uint32_t* a, uint32_t b0, uint32_t b1) {
    asm volatile(
        "mma.sync.aligned.m16n8k16.row.col.f32.bf16.bf16.f32 "
        "{%0,%1,%2,%3},{%4,%5,%6,%7},{%8,%9},{%0,%1,%2,%3};"
        : "+f"(c[0]), "+f"(c[1]), "+f"(c[2]), "+f"(c[3])
        : "r"(a[0]), "r"(a[1]), "r"(a[2]), "r"(a[3]), "r"(b0), "r"(b1));
}
__device__ __forceinline__ void ldsm4(uint32_t& r0, uint32_t& r1, uint32_t& r2, uint32_t& r3,
                                      uint32_t addr) {
    asm volatile("ldmatrix.sync.aligned.m8n8.x4.shared.b16 {%0,%1,%2,%3}, [%4];"
        : "=r"(r0), "=r"(r1), "=r"(r2), "=r"(r3) : "r"(addr));
}
__device__ __forceinline__ void stsm4(uint32_t addr, uint32_t r0, uint32_t r1,
                                      uint32_t r2, uint32_t r3) {
    asm volatile("stmatrix.sync.aligned.m8n8.x4.shared.b16 [%0], {%1,%2,%3,%4};"
        :: "r"(addr), "r"(r0), "r"(r1), "r"(r2), "r"(r3));
}
__device__ __forceinline__ void cp16(uint32_t saddr, const void* gaddr) {
    asm volatile("cp.async.cg.shared.global [%0], [%1], 16;" :: "r"(saddr), "l"(gaddr));
}
__device__ __forceinline__ void cp_commit() { asm volatile("cp.async.commit_group;"); }
template<int N> __device__ __forceinline__ void cp_wait() {
    asm volatile("cp.async.wait_group %0;" :: "n"(N));
}
__device__ __forceinline__ uint32_t packbf(float a, float b) {
    __nv_bfloat162 h = __floats2bfloat162_rn(a, b);
    return *(uint32_t*)&h;
}

// ---------------------------------------------------------------------------
// Tensor-core GEMM (TF32, cp.async 3-stage, dynamic smem): C = A @ W^T + bias.
// BM=128, BN=128, BK=16. 8 warps (4M x 2N), warp tile 32x64.
// ---------------------------------------------------------------------------
#define AST 20
#define GEMM_SMEM (3*2*128*AST*4)   // 61440 bytes
template<int MODE, bool CONCAT>
__global__ __launch_bounds__(256) void gemm_tc(
    const float* __restrict__ A, const float* __restrict__ A2,
    const float* __restrict__ W, const float* __restrict__ bias,
    float* __restrict__ C, const float* __restrict__ res,
    int M, int N, int K)
{
    extern __shared__ float dsm[];
    float* Asm = dsm;                  // [3][128*AST]
    float* Bsm = dsm + 3*128*AST;      // [3][128*AST]
    const int t = threadIdx.x;
    const int w = t >> 5, wm = w & 3, wn = w >> 2;
    const int lane = t & 31, lr4 = lane >> 2, lc4 = lane & 3;
    const int m0 = blockIdx.y << 7, n0 = blockIdx.x << 7;

    float acc[2][8][4] = {};

    const int ldr = t >> 1;
    const int ldc = (t & 1) << 3;

    uint32_t sA = (uint32_t)__cvta_generic_to_shared(Asm);
    uint32_t sB = (uint32_t)__cvta_generic_to_shared(Bsm);
    const uint32_t stg = 128*AST*4;

    auto issue_stage = [&](int k0, int buf) {
        int kk = k0 + ldc;
        const float* asrc;
        if (CONCAT) asrc = (kk >= 256) ? (A2 + (size_t)(m0 + ldr) * 256 + kk - 256)
                                       : (A  + (size_t)(m0 + ldr) * 256 + kk);
        else        asrc = A + (size_t)(m0 + ldr) * K + kk;
        uint32_t da = sA + buf*stg + (ldr*AST + ldc)*4;
        cp16(da,      asrc);
        cp16(da + 16, asrc + 4);
        const float* bsrc = W + (size_t)(n0 + ldr) * K + k0 + ldc;
        uint32_t db = sB + buf*stg + (ldr*AST + ldc)*4;
        cp16(db,      bsrc);
        cp16(db + 16, bsrc + 4);
        cp_commit();
    };

    issue_stage(0, 0);
    issue_stage(16, 1);

    const int niters = K >> 4;   // always >= 2 here
    int cur = 0;
    for (int it = 0; it < niters; it++) {
        cp_wait<1>();
        __syncthreads();
        if (it + 2 < niters) issue_stage((it + 2) << 4, (it + 2) % 3);

        const uint32_t* Ac = (const uint32_t*)(Asm + cur*128*AST);
        const uint32_t* Bc = (const uint32_t*)(Bsm + cur*128*AST);
        #pragma unroll
        for (int ks = 0; ks < 2; ks++) {
            const int kb = ks << 3;
            uint32_t a[2][4];
            #pragma unroll
            for (int mi = 0; mi < 2; mi++) {
                int r = wm*32 + mi*16 + lr4, c = kb + lc4;
                a[mi][0] = Ac[r*AST + c];     a[mi][1] = Ac[(r+8)*AST + c];
                a[mi][2] = Ac[r*AST + c + 4]; a[mi][3] = Ac[(r+8)*AST + c + 4];
            }
            #pragma unroll
            for (int ni = 0; ni < 8; ni++) {
                int r = wn*64 + ni*8 + lr4, c = kb + lc4;
                uint32_t b0 = Bc[r*AST + c], b1 = Bc[r*AST + c + 4];
                mma8(acc[0][ni], a[0], b0, b1);
                mma8(acc[1][ni], a[1], b0, b1);
            }
        }
        __syncthreads();
        cur = (cur + 1 == 3) ? 0 : cur + 1;
    }

    #pragma unroll
    for (int mi = 0; mi < 2; mi++) {
        #pragma unroll
        for (int ni = 0; ni < 8; ni++) {
            int gm = m0 + wm*32 + mi*16 + lr4;
            int gn = n0 + wn*64 + ni*8 + 2*lc4;
            float b0 = bias[gn], b1 = bias[gn+1];
            float v00 = acc[mi][ni][0] + b0, v01 = acc[mi][ni][1] + b1;
            float v10 = acc[mi][ni][2] + b0, v11 = acc[mi][ni][3] + b1;
            if (MODE == 2) {
                const float* r0 = res + (size_t)gm * N + gn;
                const float* r1 = res + (size_t)(gm+8) * N + gn;
                v00 += r0[0]; v01 += r0[1]; v10 += r1[0]; v11 += r1[1];
            }
            *(float2*)(C + (size_t)gm * N + gn)     = make_float2(v00, v01);
            *(float2*)(C + (size_t)(gm+8) * N + gn) = make_float2(v10, v11);
        }
    }
}

// ---------------------------------------------------------------------------
// Repack qkv [M,768] -> bf16 Q (roped + scaled by 0.125*log2e), K (roped), V.
// qkv col = h*192 + d*3 + c ; pair (q0,k0,v0,q1,k1,v1) contiguous at h*192+6*d2
// ---------------------------------------------------------------------------
__global__ __launch_bounds__(256) void repack_rope_kernel(const float* __restrict__ kp)
{
    int idx = blockIdx.x * blockDim.x + threadIdx.x;   // B*H*S*32 pairs
    int d2 = idx & 31;
    int s  = (idx >> 5) & (SL - 1);
    int h  = (idx >> 16) & (HN - 1);
    int b  = idx >> 18;

    int gm = b * SL + s;
    const float* src = g_qkv + (size_t)gm * 768 + h * 192 + 6 * d2;
    float q0 = src[0], k0 = src[1], v0 = src[2];
    float q1 = src[3], k1 = src[4], v1 = src[5];

    const int SIN_OFF = BD * SL * DH;
    int kb = (b * SL + s) * DH + (d2 << 1);
    float c0 = kp[kb],           c1 = kp[kb + 1];
    float s0 = kp[SIN_OFF + kb], s1 = kp[SIN_OFF + kb + 1];

    int base = (((b * HN + h) * SL) + s) * DH + (d2 << 1);
    const float scale = 0.125f * 1.4426950408889634f;   // Dh^-0.5 * log2(e)
    *(__nv_bfloat162*)&g_Qh[base] =
        __floats2bfloat162_rn((q0*c0 - q1*s0)*scale, (q1*c1 + q0*s1)*scale);
    *(__nv_bfloat162*)&g_Kh[base] =
        __floats2bfloat162_rn(k0*c0 - k1*s0, k1*c1 + k0*s1);
    *(__nv_bfloat162*)&g_Vr[base] = __floats2bfloat162_rn(v0, v1);
}

// ---------------------------------------------------------------------------
// V transpose: g_Vr [bh][s][d] -> g_Vt [bh][d][s], 64x64 smem tiles
// ---------------------------------------------------------------------------
__global__ __launch_bounds__(256) void vtrans_kernel()
{
    __shared__ uint32_t tile[64*33];
    const int t = threadIdx.x;
    const int bh = blockIdx.y;
    const int s0 = blockIdx.x << 6;

    {
        int sr = t >> 2, wc = (t & 3) * 8;
        const uint32_t* src = (const uint32_t*)(g_Vr + (size_t)bh*SL*DH + (size_t)(s0+sr)*DH) + wc;
        #pragma unroll
        for (int i = 0; i < 8; i++) tile[sr*33 + wc + i] = src[i];
    }
    __syncthreads();
    {
        int d = t >> 2, sc = (t & 3) * 16;
        uint32_t outw[8];
        #pragma unroll
        for (int j = 0; j < 8; j++) {
            uint32_t w0 = tile[(sc + 2*j    )*33 + (d >> 1)];
            uint32_t w1 = tile[(sc + 2*j + 1)*33 + (d >> 1)];
            uint32_t lo = (d & 1) ? (w0 >> 16) : (w0 & 0xffffu);
            uint32_t hi = (d & 1) ? (w1 >> 16) : (w1 & 0xffffu);
            outw[j] = lo | (hi << 16);
        }
        uint32_t* dst = (uint32_t*)(g_Vt + (size_t)bh*DH*SL + (size_t)d*SL + s0 + sc);
        *(uint4*)dst       = make_uint4(outw[0], outw[1], outw[2], outw[3]);
        *(uint4*)(dst + 4) = make_uint4(outw[4], outw[5], outw[6], outw[7]);
    }
}

// ---------------------------------------------------------------------------
// Flash attention, bf16 m16n8k16 + ldmatrix/stmatrix, max-free softmax (exp2),
// cp.async 2-stage K/V. CTA: 64 queries x 64-key tiles. 8 warps: 4(M) x 2(N).
// ---------------------------------------------------------------------------
#define KW 36   // smem row stride in 4B words (72 bf16)
__global__ __launch_bounds__(256) void attn_kernel(float* __restrict__ ctx)
{
    __shared__ uint32_t Ks[2][64*KW];
    __shared__ uint32_t Vts[2][64*KW];
    __shared__ uint32_t Ps[64*KW];
    __shared__ float lsum[2][64];

    const int t = threadIdx.x;
    const int w = t >> 5, wm = w & 3, wn = w >> 2;
    const int lane = t & 31, g = lane >> 2, tg = lane & 3;
    const int r8 = lane & 7;
    const int selA = (lane >> 3) & 1;    // matrix pair selector (m1/m3)
    const int selB = (lane >> 4) & 1;    // matrix half selector (m2/m3)
    const int bh = blockIdx.y;
    const int m0 = blockIdx.x << 6;

    const __nv_bfloat16* Qb  = g_Qh + (size_t)bh * SL * DH;
    const __nv_bfloat16* Kb  = g_Kh + (size_t)bh * SL * DH;
    const __nv_bfloat16* Vtb = g_Vt + (size_t)bh * DH * SL;

    // Q fragments in registers: 4 k-steps x 4 regs (bf16 pairs)
    uint32_t qf[4][4];
    {
        const uint32_t* Qw = (const uint32_t*)Qb;   // 32 words per row
        int r = m0 + wm*16 + g;
        #pragma unroll
        for (int kk = 0; kk < 4; kk++) {
            qf[kk][0] = Qw[(size_t)r    *32 + kk*8 + tg];
            qf[kk][1] = Qw[(size_t)(r+8)*32 + kk*8 + tg];
            qf[kk][2] = Qw[(size_t)r    *32 + kk*8 + tg + 4];
            qf[kk][3] = Qw[(size_t)(r+8)*32 + kk*8 + tg + 4];
        }
    }

    const int ldrow = t >> 2, lb = (t & 3) * 32;
    uint32_t sK = (uint32_t)__cvta_generic_to_shared(&Ks[0][0]);
    uint32_t sV = (uint32_t)__cvta_generic_to_shared(&Vts[0][0]);
    uint32_t sP = (uint32_t)__cvta_generic_to_shared(&Ps[0]);
    const uint32_t stage = 64*KW*4;

    auto issue_kv = [&](int n0, int buf) {
        const char* kg = (const char*)(Kb + (size_t)(n0 + ldrow) * DH) + lb;
        uint32_t dk = sK + buf*stage + ldrow*144 + lb;
        cp16(dk, kg); cp16(dk + 16, kg + 16);
        const char* vg = (const char*)(Vtb + (size_t)ldrow * SL + n0) + lb;
        uint32_t dv = sV + buf*stage + ldrow*144 + lb;
        cp16(dv, vg); cp16(dv + 16, vg + 16);
        cp_commit();
    };

    issue_kv(0, 0);

    float o[4][4] = {};
    float l0 = 0.f, l1 = 0.f;

    // per-lane ldmatrix/stmatrix address offsets (in words)
    const int rowB = r8 + selB*8;        // B-frags (K, Vt): rows, +8 for ni+1 half
    const int colB = selA*4;             // B-frags: k-chunk half
    const int rowA = r8 + selA*8;        // A-frags (P): row block
    const int colA = selB*4;             // A-frags: k-chunk half
    const int prow = wm*16 + r8 + selA*8;       // stmatrix rows
    const int pcolS = wn*16 + selB*4;           // stmatrix col base (+ni*4)

    for (int n0 = 0; n0 < SL; n0 += 64) {
        const int cur = (n0 >> 6) & 1;
        cp_wait<0>();
        __syncthreads();   // K/V ready; prev-iter PV reads of Ps done
        if (n0 + 64 < SL) issue_kv(n0 + 64, cur ^ 1);

        const uint32_t sKc = sK + cur*stage;
        const uint32_t sVc = sV + cur*stage;

        // S = Q K^T  (warp tile 16 x 32)
        float s[4][4] = {};
        #pragma unroll
        for (int kk = 0; kk < 4; kk++) {
            #pragma unroll
            for (int nip = 0; nip < 4; nip += 2) {
                uint32_t b0a, b1a, b0b, b1b;
                ldsm4(b0a, b1a, b0b, b1b,
                      sKc + (uint32_t)(((wn*32 + nip*8 + rowB)*KW + kk*8 + colB) * 4));
                mma16(s[nip],   qf[kk], b0a, b1a);
                mma16(s[nip+1], qf[kk], b0b, b1b);
            }
        }

        // P = exp2(S) (log2e folded into Q scale), partial row sums
        float rs0 = 0.f, rs1 = 0.f;
        #pragma unroll
        for (int ni = 0; ni < 4; ni++) {
            s[ni][0] = exp2f(s[ni][0]); s[ni][1] = exp2f(s[ni][1]);
            s[ni][2] = exp2f(s[ni][2]); s[ni][3] = exp2f(s[ni][3]);
            rs0 += s[ni][0] + s[ni][1];
            rs1 += s[ni][2] + s[ni][3];
        }
        rs0 += __shfl_xor_sync(0xffffffffu, rs0, 1);
        rs0 += __shfl_xor_sync(0xffffffffu, rs0, 2);
        rs1 += __shfl_xor_sync(0xffffffffu, rs1, 1);
        rs1 += __shfl_xor_sync(0xffffffffu, rs1, 2);
        l0 += rs0; l1 += rs1;

        // store P via stmatrix (bf16 pairs)
        #pragma unroll
        for (int nip = 0; nip < 4; nip += 2) {
            stsm4(sP + (uint32_t)((prow*KW + pcolS + nip*4) * 4),
                  packbf(s[nip][0],   s[nip][1]),   packbf(s[nip][2],   s[nip][3]),
                  packbf(s[nip+1][0], s[nip+1][1]), packbf(s[nip+1][2], s[nip+1][3]));
        }
        __syncthreads();

        // O += P V  (warp tile 16 x 32 over d)
        #pragma unroll
        for (int kk = 0; kk < 4; kk++) {
            uint32_t a[4];
            ldsm4(a[0], a[1], a[2], a[3],
                  sP + (uint32_t)(((wm*16 + rowA)*KW + kk*8 + colA) * 4));
            #pragma unroll
            for (int nip = 0; nip < 4; nip += 2) {
                uint32_t b0a, b1a, b0b, b1b;
                ldsm4(b0a, b1a, b0b, b1b,
                      sVc + (uint32_t)(((wn*32 + nip*8 + rowB)*KW + kk*8 + colB) * 4));
                mma16(o[nip],   a, b0a, b1a);
                mma16(o[nip+1], a, b0b, b1b);
            }
        }
    }

    // combine row sums across the 2 N-warps
    {
        int pr = wm*16 + g;
        if (tg == 0) { lsum[wn][pr] = l0; lsum[wn][pr + 8] = l1; }
    }
    __syncthreads();
    {
        int pr = wm*16 + g;
        float inv0 = 1.0f / (lsum[0][pr]     + lsum[1][pr]);
        float inv1 = 1.0f / (lsum[0][pr + 8] + lsum[1][pr + 8]);
        const int b = bh >> 2, h = bh & 3;
        size_t r0 = (size_t)(b * SL + m0 + pr) * DM + h * DH;
        size_t r1 = r0 + 8 * DM;
        #pragma unroll
        for (int ni = 0; ni < 4; ni++) {
            int d = wn*32 + ni*8 + 2*tg;
            *(float2*)(ctx + r0 + d) = make_float2(o[ni][0]*inv0, o[ni][1]*inv0);
            *(float2*)(ctx + r1 + d) = make_float2(o[ni][2]*inv1, o[ni][3]*inv1);
        }
    }
}

// ---------------------------------------------------------------------------
// LayerNorm (biased var) + exact GELU, in place on g_ff rows of 512
// ---------------------------------------------------------------------------
__global__ __launch_bounds__(256) void ln_gelu_kernel(const float* __restrict__ g,
                                                      const float* __restrict__ bb)
{
    int row = blockIdx.x;
    float* xr = g_ff + (size_t)row * 512;
    int t = threadIdx.x;
    float v0 = xr[t], v1 = xr[t + 256];
    float sum = v0 + v1;
    float sq  = v0 * v0 + v1 * v1;
    #pragma unroll
    for (int off = 16; off > 0; off >>= 1) {
        sum += __shfl_xor_sync(0xffffffffu, sum, off);
        sq  += __shfl_xor_sync(0xffffffffu, sq,  off);
    }
    __shared__ float ssum[8], ssq[8];
    __shared__ float smean, srstd;
    int w = t >> 5;
    if ((t & 31) == 0) { ssum[w] = sum; ssq[w] = sq; }
    __syncthreads();
    if (t == 0) {
        float S = 0.f, Q = 0.f;
        #pragma unroll
        for (int i = 0; i < 8; i++) { S += ssum[i]; Q += ssq[i]; }
        float mean = S * (1.0f / 512.0f);
        float var  = Q * (1.0f / 512.0f) - mean * mean;
        smean = mean;
        srstd = rsqrtf(var + 1e-5f);
    }
    __syncthreads();
    float mean = smean, rstd = srstd;

    float y0 = (v0 - mean) * rstd * g[t] + bb[t];
    float y1 = (v1 - mean) * rstd * g[t + 256] + bb[t + 256];
    xr[t]       = 0.5f * y0 * (1.0f + erff(y0 * 0.70710678118654752f));
    xr[t + 256] = 0.5f * y1 * (1.0f + erff(y1 * 0.70710678118654752f));
}

// ---------------------------------------------------------------------------
extern "C" void kernel_launch(void* const* d_in, const int* in_sizes, int n_in,
                              void* d_out, int out_size)
{
    (void)in_sizes; (void)n_in; (void)out_size;
    const float* desc   = (const float*)d_in[0];
    const float* kp     = (const float*)d_in[1];
    const float* Wqkv_w = (const float*)d_in[2];
    const float* Wqkv_b = (const float*)d_in[3];
    const float* Wo_w   = (const float*)d_in[4];
    const float* Wo_b   = (const float*)d_in[5];
    const float* W1_w   = (const float*)d_in[6];
    const float* W1_b   = (const float*)d_in[7];
    const float* ln_g   = (const float*)d_in[8];
    const float* ln_b   = (const float*)d_in[9];
    const float* W2_w   = (const float*)d_in[10];
    const float* W2_b   = (const float*)d_in[11];
    float* out = (float*)d_out;

    float *pqkv = nullptr, *pctx = nullptr, *pmsg = nullptr, *pff = nullptr;
    cudaGetSymbolAddress((void**)&pqkv, g_qkv);
    cudaGetSymbolAddress((void**)&pctx, g_ctx);
    cudaGetSymbolAddress((void**)&pmsg, g_msg);
    cudaGetSymbolAddress((void**)&pff,  g_ff);

    // allow >48KB dynamic smem for the GEMMs (idempotent host calls)
    cudaFuncSetAttribute(gemm_tc<0, false>, cudaFuncAttributeMaxDynamicSharedMemorySize, GEMM_SMEM);
    cudaFuncSetAttribute(gemm_tc<0, true>,  cudaFuncAttributeMaxDynamicSharedMemorySize, GEMM_SMEM);
    cudaFuncSetAttribute(gemm_tc<2, false>, cudaFuncAttributeMaxDynamicSharedMemorySize, GEMM_SMEM);

    // 1. QKV projection
    gemm_tc<0, false><<<dim3(768 / 128, MR / 128), 256, GEMM_SMEM>>>(
        desc, nullptr, Wqkv_w, Wqkv_b, pqkv, nullptr, MR, 768, 256);

    // 2. Repack to bf16 [B,H,S,Dh] + RoPE (+scale on Q)
    repack_rope_kernel<<<(BD * HN * SL * 32) / 256, 256>>>(kp);

    // 2b. V transpose -> [B,H,Dh,S]
    vtrans_kernel<<<dim3(SL / 64, BD * HN), 256>>>();

    // 3. Attention -> ctx [B,S,D]
    attn_kernel<<<dim3(SL / 64, BD * HN), 256>>>(pctx);

    // 4. message = ctx @ Wo^T + b
    gemm_tc<0, false><<<dim3(DM / 128, MR / 128), 256, GEMM_SMEM>>>(
        pctx, nullptr, Wo_w, Wo_b, pmsg, nullptr, MR, DM, DM);

    // 5. ff = concat(desc, msg) @ W1^T + b
    gemm_tc<0, true><<<dim3(512 / 128, MR / 128), 256, GEMM_SMEM>>>(
        desc, pmsg, W1_w, W1_b, pff, nullptr, MR, 512, 512);

    // 6. LayerNorm + GELU in place
    ln_gelu_kernel<<<MR, 256>>>(ln_g, ln_b);

    // 7. out = desc + ff @ W2^T + b
    gemm_tc<2, false><<<dim3(DM / 128, MR / 128), 256, GEMM_SMEM>>>(
        pff, nullptr, W2_w, W2_b, out, desc, MR, DM, 512);
}